// round 14
// baseline (speedup 1.0000x reference)
#include <cuda_runtime.h>
#include <cuda_bf16.h>
#include <math.h>

// Problem constants
#define BB   2
#define NN   2048
#define MM   128
#define HH   16
#define DD   64
#define IND  1024
#define CTXD 768
#define ROWS (BB*NN)          // 4096
#define KVW  (2*HH*DD)        // 2048
#define KEXT 129              // 1 null + 128 ctx keys

// attention tiling
#define NKEYS  2240           // 2048 self + 129 ext, padded to 35*64
#define NTILES 35
#define LIMIT  2177
#define KVPITCH 72            // K/V smem pitch: conflict-free LDS.64 frag loads
#define PPITCH  68            // P smem pitch: conflict-free scalar loads

// mma gemm tiling (R6-proven: 8 warps, 64x32 warp tiles, 256 threads)
#define APITCH 20
#define BPITCH 136
#define ATILE  (128*APITCH)
#define BTILE  (16*BPITCH)

// ---------------- scratch (static device globals; no allocation) -------------
__device__ float g_xn   [ROWS*IND];
__device__ float g_q    [ROWS*HH*DD];
__device__ float g_kext [BB*KEXT*DD];
__device__ float g_vext [BB*KEXT*DD];
__device__ float g_kt   [BB*HH*NKEYS*DD];   // K packed, d-interleaved
__device__ float g_vt   [BB*HH*DD*NKEYS];   // V^T packed, key-interleaved
__device__ float g_ahi  [ROWS*HH*DD];       // attn out hi (tf32)
__device__ float g_alo  [ROWS*HH*DD];       // attn out lo (tf32)
__device__ float g_proj [ROWS*IND];
__device__ float g_wq   [IND*HH*DD];        // tf32-rounded weights
__device__ float g_wkv  [IND*KVW];
__device__ float g_wout [HH*DD*IND];

// ---------------- helpers ------------------------------------------------------
__device__ __forceinline__ unsigned f2tf32(float x) {
    unsigned r; asm("cvt.rna.tf32.f32 %0, %1;" : "=r"(r) : "f"(x)); return r;
}
__device__ __forceinline__ float tf32f(float x) {
    return __uint_as_float(f2tf32(x));
}
// interleave within 8-group: pairs (c, c+4) become adjacent (2c, 2c+1)
__device__ __forceinline__ int il8(int c)  { return ((c & 3) << 1) | ((c >> 2) & 1); }
__device__ __forceinline__ int ilc8(int c) { return (c & ~7) | il8(c & 7); }

#define MMA_TF32(c, a, b0_, b1_)                                               \
    asm volatile("mma.sync.aligned.m16n8k8.row.col.f32.tf32.tf32.f32 "         \
                 "{%0,%1,%2,%3}, {%4,%5,%6,%7}, {%8,%9}, {%0,%1,%2,%3};"       \
                 : "+f"((c)[0]), "+f"((c)[1]), "+f"((c)[2]), "+f"((c)[3])      \
                 : "r"((a)[0]), "r"((a)[1]), "r"((a)[2]), "r"((a)[3]),         \
                   "r"(b0_), "r"(b1_))

#define CP16(dst_u32, src_ptr)                                                 \
    asm volatile("cp.async.cg.shared.global [%0], [%1], 16;"                   \
                 :: "r"(dst_u32), "l"(src_ptr))
#define CP_COMMIT() asm volatile("cp.async.commit_group;")

// ---------------- block reduction helper -------------------------------------
__device__ __forceinline__ float block_reduce_sum(float v, float* sbuf) {
    __syncthreads();
    int lane = threadIdx.x & 31, warp = threadIdx.x >> 5;
    #pragma unroll
    for (int o = 16; o; o >>= 1) v += __shfl_xor_sync(0xffffffffu, v, o);
    if (lane == 0) sbuf[warp] = v;
    __syncthreads();
    int nw = (blockDim.x + 31) >> 5;
    v = (threadIdx.x < nw) ? sbuf[threadIdx.x] : 0.0f;
    if (warp == 0) {
        #pragma unroll
        for (int o = 16; o; o >>= 1) v += __shfl_xor_sync(0xffffffffu, v, o);
        if (lane == 0) sbuf[0] = v;
    }
    __syncthreads();
    return sbuf[0];
}

// ---------------- layernorm (one block per row); rnd=1 -> tf32-rounded out ----
__global__ void ln_kernel(const float* __restrict__ in, float* __restrict__ out,
                          const float* __restrict__ g, const float* __restrict__ b,
                          int C, int rnd) {
    __shared__ float sbuf[32];
    const float* x = in + (size_t)blockIdx.x * C;
    float s = 0.f, s2 = 0.f;
    for (int i = threadIdx.x; i < C; i += blockDim.x) {
        float v = x[i]; s += v; s2 += v * v;
    }
    s  = block_reduce_sum(s,  sbuf);
    s2 = block_reduce_sum(s2, sbuf);
    float mean = s / C;
    float rstd = rsqrtf(s2 / C - mean * mean + 1e-5f);
    float* o = out + (size_t)blockIdx.x * C;
    for (int i = threadIdx.x; i < C; i += blockDim.x) {
        float v = (x[i] - mean) * rstd * g[i] + b[i];
        o[i] = rnd ? tf32f(v) : v;
    }
}

// ---------------- pre-round weights to tf32 (one pass, 4M elems) --------------
__global__ void cvtw_kernel(const float* __restrict__ wq, const float* __restrict__ wkv,
                            const float* __restrict__ wout,
                            float* __restrict__ oq, float* __restrict__ okv,
                            float* __restrict__ oout) {
    const int S1 = IND * HH * DD;      // 1M
    const int S2 = IND * KVW;          // 2M
    int i = blockIdx.x * 256 + threadIdx.x;
    if (i < S1) oq[i] = tf32f(wq[i]);
    else if (i < S1 + S2) okv[i - S1] = tf32f(wkv[i - S1]);
    else oout[i - S1 - S2] = tf32f(wout[i - S1 - S2]);
}

// ---------------- ctx branch: LN(768) + GEMV(768x128) fused --------------------
__global__ void ctx_kernel(const float* __restrict__ c_emb,
                           const float* __restrict__ g, const float* __restrict__ b,
                           const float* __restrict__ W,
                           const float* __restrict__ bctx,
                           float* __restrict__ kext, float* __restrict__ vext) {
    __shared__ float row[CTXD];
    __shared__ float sbuf[32];
    int rid = blockIdx.x;
    int bb = rid >> 7, m = rid & 127;
    const float* x = c_emb + (size_t)rid * CTXD;
    float s = 0.f, s2 = 0.f;
    for (int i = threadIdx.x; i < CTXD; i += blockDim.x) {
        float v = x[i]; row[i] = v; s += v; s2 += v * v;
    }
    s  = block_reduce_sum(s,  sbuf);
    s2 = block_reduce_sum(s2, sbuf);
    float mean = s / CTXD;
    float rstd = rsqrtf(s2 / CTXD - mean * mean + 1e-5f);
    for (int i = threadIdx.x; i < CTXD; i += blockDim.x)
        row[i] = (row[i] - mean) * rstd * g[i] + b[i];
    __syncthreads();
    if (threadIdx.x < 128) {
        int j = threadIdx.x;
        float acc = bctx[j];
        #pragma unroll 8
        for (int d = 0; d < CTXD; d++) acc += row[d] * W[d * 128 + j];
        if (j < DD) kext[((size_t)bb * KEXT + m + 1) * DD + j] = acc;
        else        vext[((size_t)bb * KEXT + m + 1) * DD + (j - DD)] = acc;
    }
}

// ---------------- pack EXT region (keys 2048..2239) into Kp / Vt ---------------
// Interleaved layouts. Null row (key 2048) comes straight from null_kv.
__global__ void pack_ext_kernel(const float* __restrict__ kext,
                                const float* __restrict__ vext,
                                const float* __restrict__ null_kv,
                                float* __restrict__ Kp, float* __restrict__ Vt) {
    const int NE = NKEYS - NN;            // 192
    int idx = blockIdx.x * 256 + threadIdx.x;
    int d  = idx & 63;
    int kl = (idx >> 6) % NE;
    int bh = idx / (NE * 64);
    int b = bh >> 4;
    int key = NN + kl;
    float kvval = 0.f, vvval = 0.f;
    if (kl == 0) {
        kvval = tf32f(null_kv[d]);
        vvval = tf32f(null_kv[DD + d]);
    } else if (key < LIMIT) {
        size_t off = ((size_t)b * KEXT + kl) * DD + d;
        kvval = tf32f(kext[off]);
        vvval = tf32f(vext[off]);
    }
    Kp[((size_t)bh * NKEYS + key) * DD + ilc8(d)] = kvval;
    Vt[((size_t)bh * DD + d) * NKEYS + ilc8(key)] = vvval;
}

// ---------------- tf32 mma GEMM: C = A(MxK) x B(KxN), row-major -----------------
// Inputs are PRE-ROUNDED tf32 bits; staging is pure cp.async copy.
// SPLITA=2 consumes a second pre-split lo-channel A (Alo).
// MODE=0: write C.  MODE=1: KV-pack epilogue (interleaved Kp/Vt).
template<int SPLITA, int MODE>
__global__ __launch_bounds__(256) void mma_gemm(
        const float* __restrict__ A, const float* __restrict__ Alo,
        const float* __restrict__ B, float* __restrict__ C,
        int M, int N, int K,
        float* __restrict__ Kp, float* __restrict__ Vt) {
    extern __shared__ float smf[];
    const int PER = SPLITA * ATILE + BTILE;

    int tid = threadIdx.x;
    int w = tid >> 5, lane = tid & 31, g = lane >> 2, t = lane & 3;
    int wm = (w >> 2) * 64, wn = (w & 3) * 32;

    const float* Ab  = A + (size_t)(blockIdx.y * 128) * K;
    const float* Alb = (SPLITA == 2) ? (Alo + (size_t)(blockIdx.y * 128) * K) : nullptr;
    const float* Bb  = B + (size_t)(blockIdx.x * 128);

    int aRow = tid >> 1,  aCol = (tid & 1) * 8;
    int bRow = tid >> 4,  bCol = (tid & 15) * 8;

    float acc[4][4][4];
    #pragma unroll
    for (int mi = 0; mi < 4; mi++)
        #pragma unroll
        for (int nj = 0; nj < 4; nj++)
            #pragma unroll
            for (int q = 0; q < 4; q++) acc[mi][nj][q] = 0.f;

    // async stage of one BK=16 slab into buffer `base`
    auto stage = [&](int kk0, float* base) {
        float* AhP = base;
        float* BhP = base + SPLITA * ATILE;
        unsigned da = (unsigned)__cvta_generic_to_shared(AhP + aRow * APITCH + aCol);
        const float* sa = Ab + (size_t)aRow * K + kk0 + aCol;
        CP16(da, sa); CP16(da + 16, sa + 4);
        if (SPLITA == 2) {
            float* AlP = base + ATILE;
            unsigned dl = (unsigned)__cvta_generic_to_shared(AlP + aRow * APITCH + aCol);
            const float* sl = Alb + (size_t)aRow * K + kk0 + aCol;
            CP16(dl, sl); CP16(dl + 16, sl + 4);
        }
        unsigned db = (unsigned)__cvta_generic_to_shared(BhP + bRow * BPITCH + bCol);
        const float* sb = Bb + (size_t)(kk0 + bRow) * N + bCol;
        CP16(db, sb); CP16(db + 16, sb + 4);
    };

    stage(0, smf);
    CP_COMMIT();

    int buf = 0;
    for (int k0 = 0; k0 < K; k0 += 16) {
        bool next = (k0 + 16) < K;
        if (next) { stage(k0 + 16, smf + (buf ^ 1) * PER); CP_COMMIT(); }
        if (next) asm volatile("cp.async.wait_group 1;");
        else      asm volatile("cp.async.wait_group 0;");
        __syncthreads();

        float* base = smf + buf * PER;
        const float* AhP = base;
        const float* AlP = base + ATILE;
        const float* BhP = base + SPLITA * ATILE;
        #pragma unroll
        for (int kk = 0; kk < 2; kk++) {
            int k = kk * 8;
            unsigned aF[4][4], bF[4][2];
            #pragma unroll
            for (int mi = 0; mi < 4; mi++) {
                const float* ap2 = AhP + (wm + mi * 16 + g) * APITCH + k + t;
                aF[mi][0] = __float_as_uint(ap2[0]);
                aF[mi][1] = __float_as_uint(ap2[8 * APITCH]);
                aF[mi][2] = __float_as_uint(ap2[4]);
                aF[mi][3] = __float_as_uint(ap2[8 * APITCH + 4]);
            }
            #pragma unroll
            for (int nj = 0; nj < 4; nj++) {
                const float* bp2 = BhP + (k + t) * BPITCH + wn + nj * 8 + g;
                bF[nj][0] = __float_as_uint(bp2[0]);
                bF[nj][1] = __float_as_uint(bp2[4 * BPITCH]);
            }
            #pragma unroll
            for (int mi = 0; mi < 4; mi++)
                #pragma unroll
                for (int nj = 0; nj < 4; nj++)
                    MMA_TF32(acc[mi][nj], aF[mi], bF[nj][0], bF[nj][1]);
            if (SPLITA == 2) {
                unsigned aL[4][4];
                #pragma unroll
                for (int mi = 0; mi < 4; mi++) {
                    const float* ap2 = AlP + (wm + mi * 16 + g) * APITCH + k + t;
                    aL[mi][0] = __float_as_uint(ap2[0]);
                    aL[mi][1] = __float_as_uint(ap2[8 * APITCH]);
                    aL[mi][2] = __float_as_uint(ap2[4]);
                    aL[mi][3] = __float_as_uint(ap2[8 * APITCH + 4]);
                }
                #pragma unroll
                for (int mi = 0; mi < 4; mi++)
                    #pragma unroll
                    for (int nj = 0; nj < 4; nj++)
                        MMA_TF32(acc[mi][nj], aL[mi], bF[nj][0], bF[nj][1]);
            }
        }
        __syncthreads();
        buf ^= 1;
    }

    if (MODE == 0) {
        #pragma unroll
        for (int mi = 0; mi < 4; mi++) {
            int row = blockIdx.y * 128 + wm + mi * 16 + g;
            #pragma unroll
            for (int nj = 0; nj < 4; nj++) {
                int col = blockIdx.x * 128 + wn + nj * 8 + 2 * t;
                *(float2*)&C[(size_t)row * N + col]       = make_float2(acc[mi][nj][0], acc[mi][nj][1]);
                *(float2*)&C[(size_t)(row + 8) * N + col] = make_float2(acc[mi][nj][2], acc[mi][nj][3]);
            }
        }
    } else {
        // KV pack epilogue with interleaved layouts.
        #pragma unroll
        for (int mi = 0; mi < 4; mi++) {
            int row = blockIdx.y * 128 + wm + mi * 16 + g;
            #pragma unroll
            for (int nj = 0; nj < 4; nj++) {
                int col = blockIdx.x * 128 + wn + nj * 8 + 2 * t;
                int s = col >> 10, h = (col >> 6) & 15, d = col & 63;   // d even
                #pragma unroll
                for (int half = 0; half < 2; half++) {
                    int tok = row + half * 8;
                    int b = tok >> 11, n = tok & 2047;
                    int bh = b * HH + h;
                    float v0 = tf32f(acc[mi][nj][half * 2 + 0]);
                    float v1 = tf32f(acc[mi][nj][half * 2 + 1]);
                    if (s == 0) {
                        size_t rb = ((size_t)bh * NKEYS + n) * DD;
                        Kp[rb + ilc8(d)]     = v0;
                        Kp[rb + ilc8(d + 1)] = v1;
                    } else {
                        int nil = ilc8(n);
                        Vt[((size_t)bh * DD + d)     * NKEYS + nil] = v0;
                        Vt[((size_t)bh * DD + d + 1) * NKEYS + nil] = v1;
                    }
                }
            }
        }
    }
}

// ---------------- flash attention on tensor cores (tf32 mma.sync) --------------
// 4 warps, 32 q-rows/warp. K/V global layouts interleaved so fragment pairs are
// adjacent -> LDS.64 frag loads (conflict-free with KVPITCH=72).
__global__ __launch_bounds__(128) void attn_mma_kernel(
        const float* __restrict__ qb,
        const float* __restrict__ Kp,
        const float* __restrict__ Vt,
        float* __restrict__ ahi, float* __restrict__ alo) {
    extern __shared__ float smem[];
    float* Ksm = smem;                        // 64 x KVPITCH
    float* Vsm = smem + 64 * KVPITCH;         // 64 x KVPITCH
    float* Psm = smem + 128 * KVPITCH;        // 128 x PPITCH
    int b = blockIdx.z, h = blockIdx.y;
    int tid = threadIdx.x;
    int w = tid >> 5, lane = tid & 31;
    int g = lane >> 2, t = lane & 3;
    int qa = blockIdx.x * 128 + w * 32 + g;

    unsigned qA[2][8][4];
    #pragma unroll
    for (int blk = 0; blk < 2; blk++) {
        const float* q0 = qb + ((size_t)(b * NN + qa + blk * 16)) * (HH * DD) + h * DD;
        const float* q1 = q0 + 8 * (HH * DD);
        #pragma unroll
        for (int kk = 0; kk < 8; kk++) {
            qA[blk][kk][0] = f2tf32(q0[kk * 8 + t]     * 0.125f);
            qA[blk][kk][1] = f2tf32(q1[kk * 8 + t]     * 0.125f);
            qA[blk][kk][2] = f2tf32(q0[kk * 8 + t + 4] * 0.125f);
            qA[blk][kk][3] = f2tf32(q1[kk * 8 + t + 4] * 0.125f);
        }
    }

    const float* Kg = Kp + ((size_t)(b * HH + h)) * NKEYS * DD;
    const float* Vg = Vt + ((size_t)(b * HH + h)) * DD * NKEYS;

    float m[4] = {-1e30f, -1e30f, -1e30f, -1e30f};
    float l[4] = {0.f, 0.f, 0.f, 0.f};
    float oC[2][8][4];
    #pragma unroll
    for (int blk = 0; blk < 2; blk++)
        #pragma unroll
        for (int nt = 0; nt < 8; nt++)
            #pragma unroll
            for (int j = 0; j < 4; j++) oC[blk][nt][j] = 0.f;

    float* Prow[4];
    #pragma unroll
    for (int r = 0; r < 4; r++) Prow[r] = &Psm[(w * 32 + r * 8 + g) * PPITCH];

    for (int tile = 0; tile < NTILES; tile++) {
        int tb = tile * 64;
        __syncthreads();
        #pragma unroll
        for (int i = 0; i < 8; i++) {
            int idx = tid + i * 128;
            int r = idx >> 4, c = (idx & 15) * 4;
            *(float4*)&Ksm[r * KVPITCH + c] = *(const float4*)&Kg[(size_t)(tb + r) * DD + c];
            *(float4*)&Vsm[r * KVPITCH + c] = *(const float4*)&Vg[(size_t)r * NKEYS + tb + c];
        }
        __syncthreads();

        // ---- S = Q * K^T (K frags are interleaved pairs -> LDS.64) ----
        float sC[2][8][4];
        #pragma unroll
        for (int blk = 0; blk < 2; blk++)
            #pragma unroll
            for (int nt = 0; nt < 8; nt++)
                #pragma unroll
                for (int j = 0; j < 4; j++) sC[blk][nt][j] = 0.f;
        #pragma unroll
        for (int kk = 0; kk < 8; kk++) {
            #pragma unroll
            for (int nt = 0; nt < 8; nt++) {
                float2 kp2 = *(const float2*)&Ksm[(nt * 8 + g) * KVPITCH + kk * 8 + 2 * t];
                unsigned b0 = __float_as_uint(kp2.x);
                unsigned b1 = __float_as_uint(kp2.y);
                MMA_TF32(sC[0][nt], qA[0][kk], b0, b1);
                MMA_TF32(sC[1][nt], qA[1][kk], b0, b1);
            }
        }

        // ---- pad mask (only the last tile has pad keys) ----
        if (tile == NTILES - 1) {
            int lim = LIMIT - tb;
            #pragma unroll
            for (int nt = 0; nt < 8; nt++) {
                int c0 = nt * 8 + 2 * t, c1 = c0 + 1;
                #pragma unroll
                for (int blk = 0; blk < 2; blk++) {
                    if (c0 >= lim) { sC[blk][nt][0] = -1e30f; sC[blk][nt][2] = -1e30f; }
                    if (c1 >= lim) { sC[blk][nt][1] = -1e30f; sC[blk][nt][3] = -1e30f; }
                }
            }
        }

        // ---- online softmax for 4 row groups ----
        #pragma unroll
        for (int blk = 0; blk < 2; blk++) {
            float tmax0 = -1e30f, tmax1 = -1e30f;
            #pragma unroll
            for (int nt = 0; nt < 8; nt++) {
                tmax0 = fmaxf(tmax0, fmaxf(sC[blk][nt][0], sC[blk][nt][1]));
                tmax1 = fmaxf(tmax1, fmaxf(sC[blk][nt][2], sC[blk][nt][3]));
            }
            tmax0 = fmaxf(tmax0, __shfl_xor_sync(0xffffffffu, tmax0, 1));
            tmax0 = fmaxf(tmax0, __shfl_xor_sync(0xffffffffu, tmax0, 2));
            tmax1 = fmaxf(tmax1, __shfl_xor_sync(0xffffffffu, tmax1, 1));
            tmax1 = fmaxf(tmax1, __shfl_xor_sync(0xffffffffu, tmax1, 2));

            int r0 = blk * 2, r1 = blk * 2 + 1;
            float mn0 = fmaxf(m[r0], tmax0), mn1 = fmaxf(m[r1], tmax1);
            float corr0 = __expf(m[r0] - mn0), corr1 = __expf(m[r1] - mn1);
            m[r0] = mn0; m[r1] = mn1;

            float ps0 = 0.f, ps1 = 0.f;
            #pragma unroll
            for (int nt = 0; nt < 8; nt++) {
                float p0 = __expf(sC[blk][nt][0] - mn0), p1 = __expf(sC[blk][nt][1] - mn0);
                float p2 = __expf(sC[blk][nt][2] - mn1), p3 = __expf(sC[blk][nt][3] - mn1);
                ps0 += p0 + p1; ps1 += p2 + p3;
                *(float2*)&Prow[r0][nt * 8 + 2 * t] = make_float2(tf32f(p0), tf32f(p1));
                *(float2*)&Prow[r1][nt * 8 + 2 * t] = make_float2(tf32f(p2), tf32f(p3));
                oC[blk][nt][0] *= corr0; oC[blk][nt][1] *= corr0;
                oC[blk][nt][2] *= corr1; oC[blk][nt][3] *= corr1;
            }
            l[r0] = l[r0] * corr0 + ps0;
            l[r1] = l[r1] * corr1 + ps1;
        }
        __syncwarp();                  // P rows are warp-private

        // ---- O += P * V (V frags interleaved -> LDS.64) ----
        #pragma unroll
        for (int kk = 0; kk < 8; kk++) {
            unsigned a0[4], a1[4];
            a0[0] = __float_as_uint(Prow[0][kk * 8 + t]);
            a0[1] = __float_as_uint(Prow[1][kk * 8 + t]);
            a0[2] = __float_as_uint(Prow[0][kk * 8 + t + 4]);
            a0[3] = __float_as_uint(Prow[1][kk * 8 + t + 4]);
            a1[0] = __float_as_uint(Prow[2][kk * 8 + t]);
            a1[1] = __float_as_uint(Prow[3][kk * 8 + t]);
            a1[2] = __float_as_uint(Prow[2][kk * 8 + t + 4]);
            a1[3] = __float_as_uint(Prow[3][kk * 8 + t + 4]);
            #pragma unroll
            for (int nd = 0; nd < 8; nd++) {
                float2 vp2 = *(const float2*)&Vsm[(nd * 8 + g) * KVPITCH + kk * 8 + 2 * t];
                unsigned b0 = __float_as_uint(vp2.x);
                unsigned b1 = __float_as_uint(vp2.y);
                MMA_TF32(oC[0][nd], a0, b0, b1);
                MMA_TF32(oC[1][nd], a1, b0, b1);
            }
        }
    }

    // ---- epilogue: write hi/lo tf32 split for the SPLITA=2 out-projection ----
    #pragma unroll
    for (int r = 0; r < 4; r++) {
        l[r] += __shfl_xor_sync(0xffffffffu, l[r], 1);
        l[r] += __shfl_xor_sync(0xffffffffu, l[r], 2);
    }
    #pragma unroll
    for (int blk = 0; blk < 2; blk++) {
        float inv0 = 1.f / l[blk * 2], inv1 = 1.f / l[blk * 2 + 1];
        size_t off = ((size_t)(b * NN + qa + blk * 16)) * (HH * DD) + h * DD;
        float* h0p = ahi + off; float* h1p = h0p + 8 * (HH * DD);
        float* l0p = alo + off; float* l1p = l0p + 8 * (HH * DD);
        #pragma unroll
        for (int nt = 0; nt < 8; nt++) {
            float v0 = oC[blk][nt][0] * inv0, v1 = oC[blk][nt][1] * inv0;
            float v2 = oC[blk][nt][2] * inv1, v3 = oC[blk][nt][3] * inv1;
            float hh0 = tf32f(v0), hh1 = tf32f(v1), hh2 = tf32f(v2), hh3 = tf32f(v3);
            *(float2*)&h0p[nt * 8 + 2 * t] = make_float2(hh0, hh1);
            *(float2*)&h1p[nt * 8 + 2 * t] = make_float2(hh2, hh3);
            *(float2*)&l0p[nt * 8 + 2 * t] = make_float2(tf32f(v0 - hh0), tf32f(v1 - hh1));
            *(float2*)&l1p[nt * 8 + 2 * t] = make_float2(tf32f(v2 - hh2), tf32f(v3 - hh3));
        }
    }
}

// ---------------- host launcher ------------------------------------------------
extern "C" void kernel_launch(void* const* d_in, const int* in_sizes, int n_in,
                              void* d_out, int out_size) {
    const float* x        = (const float*)d_in[0];
    const float* c_emb    = (const float*)d_in[1];
    const float* ln_g     = (const float*)d_in[2];
    const float* ln_b     = (const float*)d_in[3];
    const float* ctx_ln_g = (const float*)d_in[4];
    const float* ctx_ln_b = (const float*)d_in[5];
    const float* W_ctx    = (const float*)d_in[6];
    const float* b_ctx    = (const float*)d_in[7];
    const float* W_q      = (const float*)d_in[8];
    const float* W_kv     = (const float*)d_in[9];
    const float* null_kv  = (const float*)d_in[10];
    const float* W_out    = (const float*)d_in[11];
    const float* out_ln_g = (const float*)d_in[12];
    const float* out_ln_b = (const float*)d_in[13];
    float* out = (float*)d_out;

    float *xn, *qb, *kext, *vext, *kt, *vt, *ahi, *alo, *proj, *wq, *wkv, *wout;
    cudaGetSymbolAddress((void**)&xn,   g_xn);
    cudaGetSymbolAddress((void**)&qb,   g_q);
    cudaGetSymbolAddress((void**)&kext, g_kext);
    cudaGetSymbolAddress((void**)&vext, g_vext);
    cudaGetSymbolAddress((void**)&kt,   g_kt);
    cudaGetSymbolAddress((void**)&vt,   g_vt);
    cudaGetSymbolAddress((void**)&ahi,  g_ahi);
    cudaGetSymbolAddress((void**)&alo,  g_alo);
    cudaGetSymbolAddress((void**)&proj, g_proj);
    cudaGetSymbolAddress((void**)&wq,   g_wq);
    cudaGetSymbolAddress((void**)&wkv,  g_wkv);
    cudaGetSymbolAddress((void**)&wout, g_wout);

    const int smem1 = 2 * (1 * ATILE + BTILE) * 4;   // 37888 B
    const int smem2 = 2 * (2 * ATILE + BTILE) * 4;   // 58368 B
    const int smemA = (128 * KVPITCH + 128 * PPITCH) * 4;  // 71680 B
    cudaFuncSetAttribute((const void*)mma_gemm<1,0>, cudaFuncAttributeMaxDynamicSharedMemorySize, smem1);
    cudaFuncSetAttribute((const void*)mma_gemm<1,1>, cudaFuncAttributeMaxDynamicSharedMemorySize, smem1);
    cudaFuncSetAttribute((const void*)mma_gemm<2,0>, cudaFuncAttributeMaxDynamicSharedMemorySize, smem2);
    cudaFuncSetAttribute((const void*)attn_mma_kernel, cudaFuncAttributeMaxDynamicSharedMemorySize, smemA);

    // pre-round weights (independent of everything else)
    cvtw_kernel<<<(IND * HH * DD + IND * KVW + HH * DD * IND) / 256, 256>>>(
        W_q, W_kv, W_out, wq, wkv, wout);
    ln_kernel<<<ROWS, 256>>>(x, xn, ln_g, ln_b, IND, 1);
    ctx_kernel<<<BB * MM, 256>>>(c_emb, ctx_ln_g, ctx_ln_b, W_ctx, b_ctx, kext, vext);
    pack_ext_kernel<<<(BB * HH * (NKEYS - NN) * DD) / 256, 256>>>(kext, vext, null_kv, kt, vt);
    // Q projection
    mma_gemm<1,0><<<dim3((HH * DD) / 128, ROWS / 128), 256, smem1>>>(
        xn, nullptr, wq, qb, ROWS, HH * DD, IND, nullptr, nullptr);
    // KV projection with fused interleaved pack epilogue
    mma_gemm<1,1><<<dim3(KVW / 128, ROWS / 128), 256, smem1>>>(
        xn, nullptr, wkv, nullptr, ROWS, KVW, IND, kt, vt);
    // attention
    attn_mma_kernel<<<dim3(NN / 128, HH, BB), 128, smemA>>>(qb, kt, vt, ahi, alo);
    // output projection (pre-split A for accuracy)
    mma_gemm<2,0><<<dim3(IND / 128, ROWS / 128), 256, smem2>>>(
        ahi, alo, wout, proj, ROWS, IND, IND, nullptr, nullptr);
    ln_kernel<<<ROWS, 256>>>(proj, out, out_ln_g, out_ln_b, IND, 0);
}

// round 15
// speedup vs baseline: 1.0105x; 1.0105x over previous
#include <cuda_runtime.h>
#include <cuda_bf16.h>
#include <math.h>

// Problem constants
#define BB   2
#define NN   2048
#define MM   128
#define HH   16
#define DD   64
#define IND  1024
#define CTXD 768
#define ROWS (BB*NN)          // 4096
#define KVW  (2*HH*DD)        // 2048
#define KEXT 129              // 1 null + 128 ctx keys

// attention tiling
#define NKEYS  2240           // 2048 self + 129 ext, padded to 35*64
#define NTILES 35
#define LIMIT  2177
#define KVPITCH 72            // K/V smem pitch: conflict-free LDS.64 frag loads
#define PPITCH  68            // P smem pitch: conflict-free scalar loads

// mma gemm tiling (R6-proven: 8 warps, 64x32 warp tiles, 256 threads)
#define APITCH 20
#define BPITCH 136
#define ATILE  (128*APITCH)
#define BTILE  (16*BPITCH)

// ---------------- scratch (static device globals; no allocation) -------------
__device__ float g_xn  [ROWS*IND];
__device__ float g_q   [ROWS*HH*DD];
__device__ float g_kext[BB*KEXT*DD];
__device__ float g_vext[BB*KEXT*DD];
__device__ float g_kt  [BB*HH*NKEYS*DD];   // K packed, d-interleaved (tf32 bits)
__device__ float g_vt  [BB*HH*DD*NKEYS];   // V^T packed, key-interleaved (tf32 bits)
__device__ float g_attn[ROWS*HH*DD];
__device__ float g_proj[ROWS*IND];

// ---------------- tf32 helpers -------------------------------------------------
__device__ __forceinline__ unsigned f2tf32(float x) {
    unsigned r; asm("cvt.rna.tf32.f32 %0, %1;" : "=r"(r) : "f"(x)); return r;
}
__device__ __forceinline__ float tf32f(float x) {
    return __uint_as_float(f2tf32(x));
}
// interleave within 8-group: pairs (c, c+4) become adjacent (2c, 2c+1)
__device__ __forceinline__ int il8(int c)  { return ((c & 3) << 1) | ((c >> 2) & 1); }
__device__ __forceinline__ int ilc8(int c) { return (c & ~7) | il8(c & 7); }

#define MMA_TF32(c, a, b0_, b1_)                                               \
    asm volatile("mma.sync.aligned.m16n8k8.row.col.f32.tf32.tf32.f32 "         \
                 "{%0,%1,%2,%3}, {%4,%5,%6,%7}, {%8,%9}, {%0,%1,%2,%3};"       \
                 : "+f"((c)[0]), "+f"((c)[1]), "+f"((c)[2]), "+f"((c)[3])      \
                 : "r"((a)[0]), "r"((a)[1]), "r"((a)[2]), "r"((a)[3]),         \
                   "r"(b0_), "r"(b1_))

// ---------------- block reduction helper -------------------------------------
__device__ __forceinline__ float block_reduce_sum(float v, float* sbuf) {
    __syncthreads();
    int lane = threadIdx.x & 31, warp = threadIdx.x >> 5;
    #pragma unroll
    for (int o = 16; o; o >>= 1) v += __shfl_xor_sync(0xffffffffu, v, o);
    if (lane == 0) sbuf[warp] = v;
    __syncthreads();
    int nw = (blockDim.x + 31) >> 5;
    v = (threadIdx.x < nw) ? sbuf[threadIdx.x] : 0.0f;
    if (warp == 0) {
        #pragma unroll
        for (int o = 16; o; o >>= 1) v += __shfl_xor_sync(0xffffffffu, v, o);
        if (lane == 0) sbuf[0] = v;
    }
    __syncthreads();
    return sbuf[0];
}

// ---------------- layernorm (one block per row) -------------------------------
__global__ void ln_kernel(const float* __restrict__ in, float* __restrict__ out,
                          const float* __restrict__ g, const float* __restrict__ b,
                          int C) {
    __shared__ float sbuf[32];
    const float* x = in + (size_t)blockIdx.x * C;
    float s = 0.f, s2 = 0.f;
    for (int i = threadIdx.x; i < C; i += blockDim.x) {
        float v = x[i]; s += v; s2 += v * v;
    }
    s  = block_reduce_sum(s,  sbuf);
    s2 = block_reduce_sum(s2, sbuf);
    float mean = s / C;
    float rstd = rsqrtf(s2 / C - mean * mean + 1e-5f);
    float* o = out + (size_t)blockIdx.x * C;
    for (int i = threadIdx.x; i < C; i += blockDim.x)
        o[i] = (x[i] - mean) * rstd * g[i] + b[i];
}

// ---------------- ctx branch: LN(768) + GEMV(768x128) fused --------------------
__global__ void ctx_kernel(const float* __restrict__ c_emb,
                           const float* __restrict__ g, const float* __restrict__ b,
                           const float* __restrict__ W,
                           const float* __restrict__ bctx,
                           float* __restrict__ kext, float* __restrict__ vext) {
    __shared__ float row[CTXD];
    __shared__ float sbuf[32];
    int rid = blockIdx.x;
    int bb = rid >> 7, m = rid & 127;
    const float* x = c_emb + (size_t)rid * CTXD;
    float s = 0.f, s2 = 0.f;
    for (int i = threadIdx.x; i < CTXD; i += blockDim.x) {
        float v = x[i]; row[i] = v; s += v; s2 += v * v;
    }
    s  = block_reduce_sum(s,  sbuf);
    s2 = block_reduce_sum(s2, sbuf);
    float mean = s / CTXD;
    float rstd = rsqrtf(s2 / CTXD - mean * mean + 1e-5f);
    for (int i = threadIdx.x; i < CTXD; i += blockDim.x)
        row[i] = (row[i] - mean) * rstd * g[i] + b[i];
    __syncthreads();
    if (threadIdx.x < 128) {
        int j = threadIdx.x;
        float acc = bctx[j];
        #pragma unroll 8
        for (int d = 0; d < CTXD; d++) acc += row[d] * W[d * 128 + j];
        if (j < DD) kext[((size_t)bb * KEXT + m + 1) * DD + j] = acc;
        else        vext[((size_t)bb * KEXT + m + 1) * DD + (j - DD)] = acc;
    }
}

// ---------------- pack EXT region (keys 2048..2239) into Kp / Vt ---------------
// Interleaved layouts; null row folded in.
__global__ void pack_ext_kernel(const float* __restrict__ kext,
                                const float* __restrict__ vext,
                                const float* __restrict__ null_kv,
                                float* __restrict__ Kp, float* __restrict__ Vt) {
    const int NE = NKEYS - NN;            // 192
    int idx = blockIdx.x * 256 + threadIdx.x;
    int d  = idx & 63;
    int kl = (idx >> 6) % NE;
    int bh = idx / (NE * 64);
    int b = bh >> 4;
    int key = NN + kl;
    float kvval = 0.f, vvval = 0.f;
    if (kl == 0) {
        kvval = tf32f(null_kv[d]);
        vvval = tf32f(null_kv[DD + d]);
    } else if (key < LIMIT) {
        size_t off = ((size_t)b * KEXT + kl) * DD + d;
        kvval = tf32f(kext[off]);
        vvval = tf32f(vext[off]);
    }
    Kp[((size_t)bh * NKEYS + key) * DD + ilc8(d)] = kvval;
    Vt[((size_t)bh * DD + d) * NKEYS + ilc8(key)] = vvval;
}

// ---------------- tf32 mma GEMM: C = A(MxK) x B(KxN), row-major -----------------
// R13-proven loop (register prefetch, one sync/iter). tf32 rounding in staging.
// SPLITA=1: plain tf32. SPLITA=2: A split hi/lo (2 passes) for higher accuracy.
// MODE=0: write C.  MODE=1: KV-pack epilogue (INTERLEAVED Kp/Vt).
template<int SPLITA, int MODE>
__global__ __launch_bounds__(256) void mma_gemm(
        const float* __restrict__ A, const float* __restrict__ B,
        float* __restrict__ C, int M, int N, int K,
        float* __restrict__ Kp, float* __restrict__ Vt) {
    extern __shared__ float smf[];
    const int PER = SPLITA * ATILE + BTILE;

    int tid = threadIdx.x;
    int w = tid >> 5, lane = tid & 31, g = lane >> 2, t = lane & 3;
    int wm = (w >> 2) * 64, wn = (w & 3) * 32;

    const float* Ab = A + (size_t)(blockIdx.y * 128) * K;
    const float* Bb = B + (size_t)(blockIdx.x * 128);

    int aRow = tid >> 1,  aCol = (tid & 1) * 8;
    int bRow = tid >> 4,  bCol = (tid & 15) * 8;

    float acc[4][4][4];
    #pragma unroll
    for (int mi = 0; mi < 4; mi++)
        #pragma unroll
        for (int nj = 0; nj < 4; nj++)
            #pragma unroll
            for (int q = 0; q < 4; q++) acc[mi][nj][q] = 0.f;

    float4 pa0, pa1, pb0, pb1;
    {
        const float* ap = Ab + (size_t)aRow * K + aCol;
        pa0 = *(const float4*)ap; pa1 = *(const float4*)(ap + 4);
        const float* bp = Bb + (size_t)bRow * N + bCol;
        pb0 = *(const float4*)bp; pb1 = *(const float4*)(bp + 4);
    }
    // store tile 0
    {
        float* base = smf;
        float* AhP = base;
        float* BhP = base + SPLITA * ATILE;
        float4 h0 = make_float4(tf32f(pa0.x), tf32f(pa0.y), tf32f(pa0.z), tf32f(pa0.w));
        float4 h1 = make_float4(tf32f(pa1.x), tf32f(pa1.y), tf32f(pa1.z), tf32f(pa1.w));
        *(float4*)&AhP[aRow * APITCH + aCol]     = h0;
        *(float4*)&AhP[aRow * APITCH + aCol + 4] = h1;
        if (SPLITA == 2) {
            float* AlP = base + ATILE;
            *(float4*)&AlP[aRow * APITCH + aCol] =
                make_float4(tf32f(pa0.x - h0.x), tf32f(pa0.y - h0.y), tf32f(pa0.z - h0.z), tf32f(pa0.w - h0.w));
            *(float4*)&AlP[aRow * APITCH + aCol + 4] =
                make_float4(tf32f(pa1.x - h1.x), tf32f(pa1.y - h1.y), tf32f(pa1.z - h1.z), tf32f(pa1.w - h1.w));
        }
        *(float4*)&BhP[bRow * BPITCH + bCol] =
            make_float4(tf32f(pb0.x), tf32f(pb0.y), tf32f(pb0.z), tf32f(pb0.w));
        *(float4*)&BhP[bRow * BPITCH + bCol + 4] =
            make_float4(tf32f(pb1.x), tf32f(pb1.y), tf32f(pb1.z), tf32f(pb1.w));
    }
    __syncthreads();

    int buf = 0;
    for (int k0 = 0; k0 < K; k0 += 16) {
        bool next = (k0 + 16) < K;
        if (next) {
            const float* ap = Ab + (size_t)aRow * K + (k0 + 16) + aCol;
            pa0 = *(const float4*)ap; pa1 = *(const float4*)(ap + 4);
            const float* bp = Bb + (size_t)(k0 + 16 + bRow) * N + bCol;
            pb0 = *(const float4*)bp; pb1 = *(const float4*)(bp + 4);
        }
        float* base = smf + buf * PER;
        const float* AhP = base;
        const float* AlP = base + ATILE;
        const float* BhP = base + SPLITA * ATILE;
        #pragma unroll
        for (int kk = 0; kk < 2; kk++) {
            int k = kk * 8;
            unsigned aF[4][4], bF[4][2];
            #pragma unroll
            for (int mi = 0; mi < 4; mi++) {
                const float* ap2 = AhP + (wm + mi * 16 + g) * APITCH + k + t;
                aF[mi][0] = __float_as_uint(ap2[0]);
                aF[mi][1] = __float_as_uint(ap2[8 * APITCH]);
                aF[mi][2] = __float_as_uint(ap2[4]);
                aF[mi][3] = __float_as_uint(ap2[8 * APITCH + 4]);
            }
            #pragma unroll
            for (int nj = 0; nj < 4; nj++) {
                const float* bp2 = BhP + (k + t) * BPITCH + wn + nj * 8 + g;
                bF[nj][0] = __float_as_uint(bp2[0]);
                bF[nj][1] = __float_as_uint(bp2[4 * BPITCH]);
            }
            #pragma unroll
            for (int mi = 0; mi < 4; mi++)
                #pragma unroll
                for (int nj = 0; nj < 4; nj++)
                    MMA_TF32(acc[mi][nj], aF[mi], bF[nj][0], bF[nj][1]);
            if (SPLITA == 2) {
                unsigned aL[4][4];
                #pragma unroll
                for (int mi = 0; mi < 4; mi++) {
                    const float* ap2 = AlP + (wm + mi * 16 + g) * APITCH + k + t;
                    aL[mi][0] = __float_as_uint(ap2[0]);
                    aL[mi][1] = __float_as_uint(ap2[8 * APITCH]);
                    aL[mi][2] = __float_as_uint(ap2[4]);
                    aL[mi][3] = __float_as_uint(ap2[8 * APITCH + 4]);
                }
                #pragma unroll
                for (int mi = 0; mi < 4; mi++)
                    #pragma unroll
                    for (int nj = 0; nj < 4; nj++)
                        MMA_TF32(acc[mi][nj], aL[mi], bF[nj][0], bF[nj][1]);
            }
        }
        if (next) {
            float* nb = smf + (buf ^ 1) * PER;
            float* AhP2 = nb;
            float* BhP2 = nb + SPLITA * ATILE;
            float4 h0 = make_float4(tf32f(pa0.x), tf32f(pa0.y), tf32f(pa0.z), tf32f(pa0.w));
            float4 h1 = make_float4(tf32f(pa1.x), tf32f(pa1.y), tf32f(pa1.z), tf32f(pa1.w));
            *(float4*)&AhP2[aRow * APITCH + aCol]     = h0;
            *(float4*)&AhP2[aRow * APITCH + aCol + 4] = h1;
            if (SPLITA == 2) {
                float* AlP2 = nb + ATILE;
                *(float4*)&AlP2[aRow * APITCH + aCol] =
                    make_float4(tf32f(pa0.x - h0.x), tf32f(pa0.y - h0.y), tf32f(pa0.z - h0.z), tf32f(pa0.w - h0.w));
                *(float4*)&AlP2[aRow * APITCH + aCol + 4] =
                    make_float4(tf32f(pa1.x - h1.x), tf32f(pa1.y - h1.y), tf32f(pa1.z - h1.z), tf32f(pa1.w - h1.w));
            }
            *(float4*)&BhP2[bRow * BPITCH + bCol] =
                make_float4(tf32f(pb0.x), tf32f(pb0.y), tf32f(pb0.z), tf32f(pb0.w));
            *(float4*)&BhP2[bRow * BPITCH + bCol + 4] =
                make_float4(tf32f(pb1.x), tf32f(pb1.y), tf32f(pb1.z), tf32f(pb1.w));
            __syncthreads();
            buf ^= 1;
        }
    }

    if (MODE == 0) {
        #pragma unroll
        for (int mi = 0; mi < 4; mi++) {
            int row = blockIdx.y * 128 + wm + mi * 16 + g;
            #pragma unroll
            for (int nj = 0; nj < 4; nj++) {
                int col = blockIdx.x * 128 + wn + nj * 8 + 2 * t;
                *(float2*)&C[(size_t)row * N + col]       = make_float2(acc[mi][nj][0], acc[mi][nj][1]);
                *(float2*)&C[(size_t)(row + 8) * N + col] = make_float2(acc[mi][nj][2], acc[mi][nj][3]);
            }
        }
    } else {
        // KV pack epilogue with interleaved layouts.
        #pragma unroll
        for (int mi = 0; mi < 4; mi++) {
            int row = blockIdx.y * 128 + wm + mi * 16 + g;
            #pragma unroll
            for (int nj = 0; nj < 4; nj++) {
                int col = blockIdx.x * 128 + wn + nj * 8 + 2 * t;
                int s = col >> 10, h = (col >> 6) & 15, d = col & 63;   // d even
                #pragma unroll
                for (int half = 0; half < 2; half++) {
                    int tok = row + half * 8;
                    int b = tok >> 11, n = tok & 2047;
                    int bh = b * HH + h;
                    float v0 = tf32f(acc[mi][nj][half * 2 + 0]);
                    float v1 = tf32f(acc[mi][nj][half * 2 + 1]);
                    if (s == 0) {
                        size_t rb = ((size_t)bh * NKEYS + n) * DD;
                        Kp[rb + ilc8(d)]     = v0;
                        Kp[rb + ilc8(d + 1)] = v1;
                    } else {
                        int nil = ilc8(n);
                        Vt[((size_t)bh * DD + d)     * NKEYS + nil] = v0;
                        Vt[((size_t)bh * DD + d + 1) * NKEYS + nil] = v1;
                    }
                }
            }
        }
    }
}

// ---------------- flash attention on tensor cores (tf32 mma.sync) --------------
// 4 warps, 32 q-rows/warp (two 16-row A blocks). K/V interleaved -> LDS.64
// fragment loads (conflict-free at KVPITCH=72). P in separate PPITCH region.
__global__ __launch_bounds__(128) void attn_mma_kernel(
        const float* __restrict__ qb,
        const float* __restrict__ Kp,
        const float* __restrict__ Vt,
        float* __restrict__ outb) {
    extern __shared__ float smem[];
    float* Ksm = smem;                        // 64 x KVPITCH
    float* Vsm = smem + 64 * KVPITCH;         // 64 x KVPITCH
    float* Psm = smem + 128 * KVPITCH;        // 128 x PPITCH
    int b = blockIdx.z, h = blockIdx.y;
    int tid = threadIdx.x;
    int w = tid >> 5, lane = tid & 31;
    int g = lane >> 2, t = lane & 3;
    int qa = blockIdx.x * 128 + w * 32 + g;

    unsigned qA[2][8][4];
    #pragma unroll
    for (int blk = 0; blk < 2; blk++) {
        const float* q0 = qb + ((size_t)(b * NN + qa + blk * 16)) * (HH * DD) + h * DD;
        const float* q1 = q0 + 8 * (HH * DD);
        #pragma unroll
        for (int kk = 0; kk < 8; kk++) {
            qA[blk][kk][0] = f2tf32(q0[kk * 8 + t]     * 0.125f);
            qA[blk][kk][1] = f2tf32(q1[kk * 8 + t]     * 0.125f);
            qA[blk][kk][2] = f2tf32(q0[kk * 8 + t + 4] * 0.125f);
            qA[blk][kk][3] = f2tf32(q1[kk * 8 + t + 4] * 0.125f);
        }
    }

    const float* Kg = Kp + ((size_t)(b * HH + h)) * NKEYS * DD;
    const float* Vg = Vt + ((size_t)(b * HH + h)) * DD * NKEYS;

    float m[4] = {-1e30f, -1e30f, -1e30f, -1e30f};
    float l[4] = {0.f, 0.f, 0.f, 0.f};
    float oC[2][8][4];
    #pragma unroll
    for (int blk = 0; blk < 2; blk++)
        #pragma unroll
        for (int nt = 0; nt < 8; nt++)
            #pragma unroll
            for (int j = 0; j < 4; j++) oC[blk][nt][j] = 0.f;

    float* Prow[4];
    #pragma unroll
    for (int r = 0; r < 4; r++) Prow[r] = &Psm[(w * 32 + r * 8 + g) * PPITCH];

    for (int tile = 0; tile < NTILES; tile++) {
        int tb = tile * 64;
        __syncthreads();
        #pragma unroll
        for (int i = 0; i < 8; i++) {
            int idx = tid + i * 128;
            int r = idx >> 4, c = (idx & 15) * 4;
            *(float4*)&Ksm[r * KVPITCH + c] = *(const float4*)&Kg[(size_t)(tb + r) * DD + c];
            *(float4*)&Vsm[r * KVPITCH + c] = *(const float4*)&Vg[(size_t)r * NKEYS + tb + c];
        }
        __syncthreads();

        // ---- S = Q * K^T (interleaved K -> LDS.64 frag pairs) ----
        float sC[2][8][4];
        #pragma unroll
        for (int blk = 0; blk < 2; blk++)
            #pragma unroll
            for (int nt = 0; nt < 8; nt++)
                #pragma unroll
                for (int j = 0; j < 4; j++) sC[blk][nt][j] = 0.f;
        #pragma unroll
        for (int kk = 0; kk < 8; kk++) {
            #pragma unroll
            for (int nt = 0; nt < 8; nt++) {
                float2 kp2 = *(const float2*)&Ksm[(nt * 8 + g) * KVPITCH + kk * 8 + 2 * t];
                unsigned b0 = __float_as_uint(kp2.x);
                unsigned b1 = __float_as_uint(kp2.y);
                MMA_TF32(sC[0][nt], qA[0][kk], b0, b1);
                MMA_TF32(sC[1][nt], qA[1][kk], b0, b1);
            }
        }

        // ---- pad mask (only the last tile has pad keys) ----
        if (tile == NTILES - 1) {
            int lim = LIMIT - tb;
            #pragma unroll
            for (int nt = 0; nt < 8; nt++) {
                int c0 = nt * 8 + 2 * t, c1 = c0 + 1;
                #pragma unroll
                for (int blk = 0; blk < 2; blk++) {
                    if (c0 >= lim) { sC[blk][nt][0] = -1e30f; sC[blk][nt][2] = -1e30f; }
                    if (c1 >= lim) { sC[blk][nt][1] = -1e30f; sC[blk][nt][3] = -1e30f; }
                }
            }
        }

        // ---- online softmax for 4 row groups ----
        #pragma unroll
        for (int blk = 0; blk < 2; blk++) {
            float tmax0 = -1e30f, tmax1 = -1e30f;
            #pragma unroll
            for (int nt = 0; nt < 8; nt++) {
                tmax0 = fmaxf(tmax0, fmaxf(sC[blk][nt][0], sC[blk][nt][1]));
                tmax1 = fmaxf(tmax1, fmaxf(sC[blk][nt][2], sC[blk][nt][3]));
            }
            tmax0 = fmaxf(tmax0, __shfl_xor_sync(0xffffffffu, tmax0, 1));
            tmax0 = fmaxf(tmax0, __shfl_xor_sync(0xffffffffu, tmax0, 2));
            tmax1 = fmaxf(tmax1, __shfl_xor_sync(0xffffffffu, tmax1, 1));
            tmax1 = fmaxf(tmax1, __shfl_xor_sync(0xffffffffu, tmax1, 2));

            int r0 = blk * 2, r1 = blk * 2 + 1;
            float mn0 = fmaxf(m[r0], tmax0), mn1 = fmaxf(m[r1], tmax1);
            float corr0 = __expf(m[r0] - mn0), corr1 = __expf(m[r1] - mn1);
            m[r0] = mn0; m[r1] = mn1;

            float ps0 = 0.f, ps1 = 0.f;
            #pragma unroll
            for (int nt = 0; nt < 8; nt++) {
                float p0 = __expf(sC[blk][nt][0] - mn0), p1 = __expf(sC[blk][nt][1] - mn0);
                float p2 = __expf(sC[blk][nt][2] - mn1), p3 = __expf(sC[blk][nt][3] - mn1);
                ps0 += p0 + p1; ps1 += p2 + p3;
                *(float2*)&Prow[r0][nt * 8 + 2 * t] = make_float2(tf32f(p0), tf32f(p1));
                *(float2*)&Prow[r1][nt * 8 + 2 * t] = make_float2(tf32f(p2), tf32f(p3));
                oC[blk][nt][0] *= corr0; oC[blk][nt][1] *= corr0;
                oC[blk][nt][2] *= corr1; oC[blk][nt][3] *= corr1;
            }
            l[r0] = l[r0] * corr0 + ps0;
            l[r1] = l[r1] * corr1 + ps1;
        }
        __syncwarp();                  // P rows are warp-private

        // ---- O += P * V (interleaved V -> LDS.64 frag pairs) ----
        #pragma unroll
        for (int kk = 0; kk < 8; kk++) {
            unsigned a0[4], a1[4];
            a0[0] = __float_as_uint(Prow[0][kk * 8 + t]);
            a0[1] = __float_as_uint(Prow[1][kk * 8 + t]);
            a0[2] = __float_as_uint(Prow[0][kk * 8 + t + 4]);
            a0[3] = __float_as_uint(Prow[1][kk * 8 + t + 4]);
            a1[0] = __float_as_uint(Prow[2][kk * 8 + t]);
            a1[1] = __float_as_uint(Prow[3][kk * 8 + t]);
            a1[2] = __float_as_uint(Prow[2][kk * 8 + t + 4]);
            a1[3] = __float_as_uint(Prow[3][kk * 8 + t + 4]);
            #pragma unroll
            for (int nd = 0; nd < 8; nd++) {
                float2 vp2 = *(const float2*)&Vsm[(nd * 8 + g) * KVPITCH + kk * 8 + 2 * t];
                unsigned b0 = __float_as_uint(vp2.x);
                unsigned b1 = __float_as_uint(vp2.y);
                MMA_TF32(oC[0][nd], a0, b0, b1);
                MMA_TF32(oC[1][nd], a1, b0, b1);
            }
        }
    }

    // ---- epilogue ----
    #pragma unroll
    for (int r = 0; r < 4; r++) {
        l[r] += __shfl_xor_sync(0xffffffffu, l[r], 1);
        l[r] += __shfl_xor_sync(0xffffffffu, l[r], 2);
    }
    #pragma unroll
    for (int blk = 0; blk < 2; blk++) {
        float inv0 = 1.f / l[blk * 2], inv1 = 1.f / l[blk * 2 + 1];
        float* o0 = outb + ((size_t)(b * NN + qa + blk * 16)) * (HH * DD) + h * DD;
        float* o1 = o0 + 8 * (HH * DD);
        #pragma unroll
        for (int nt = 0; nt < 8; nt++) {
            *(float2*)&o0[nt * 8 + 2 * t] = make_float2(oC[blk][nt][0] * inv0, oC[blk][nt][1] * inv0);
            *(float2*)&o1[nt * 8 + 2 * t] = make_float2(oC[blk][nt][2] * inv1, oC[blk][nt][3] * inv1);
        }
    }
}

// ---------------- host launcher ------------------------------------------------
extern "C" void kernel_launch(void* const* d_in, const int* in_sizes, int n_in,
                              void* d_out, int out_size) {
    const float* x        = (const float*)d_in[0];
    const float* c_emb    = (const float*)d_in[1];
    const float* ln_g     = (const float*)d_in[2];
    const float* ln_b     = (const float*)d_in[3];
    const float* ctx_ln_g = (const float*)d_in[4];
    const float* ctx_ln_b = (const float*)d_in[5];
    const float* W_ctx    = (const float*)d_in[6];
    const float* b_ctx    = (const float*)d_in[7];
    const float* W_q      = (const float*)d_in[8];
    const float* W_kv     = (const float*)d_in[9];
    const float* null_kv  = (const float*)d_in[10];
    const float* W_out    = (const float*)d_in[11];
    const float* out_ln_g = (const float*)d_in[12];
    const float* out_ln_b = (const float*)d_in[13];
    float* out = (float*)d_out;

    float *xn, *qb, *kext, *vext, *kt, *vt, *attn, *proj;
    cudaGetSymbolAddress((void**)&xn,   g_xn);
    cudaGetSymbolAddress((void**)&qb,   g_q);
    cudaGetSymbolAddress((void**)&kext, g_kext);
    cudaGetSymbolAddress((void**)&vext, g_vext);
    cudaGetSymbolAddress((void**)&kt,   g_kt);
    cudaGetSymbolAddress((void**)&vt,   g_vt);
    cudaGetSymbolAddress((void**)&attn, g_attn);
    cudaGetSymbolAddress((void**)&proj, g_proj);

    const int smem1 = 2 * (1 * ATILE + BTILE) * 4;   // 37888 B
    const int smem2 = 2 * (2 * ATILE + BTILE) * 4;   // 58368 B
    const int smemA = (128 * KVPITCH + 128 * PPITCH) * 4;  // 71680 B
    cudaFuncSetAttribute((const void*)mma_gemm<1,0>, cudaFuncAttributeMaxDynamicSharedMemorySize, smem1);
    cudaFuncSetAttribute((const void*)mma_gemm<1,1>, cudaFuncAttributeMaxDynamicSharedMemorySize, smem1);
    cudaFuncSetAttribute((const void*)mma_gemm<2,0>, cudaFuncAttributeMaxDynamicSharedMemorySize, smem2);
    cudaFuncSetAttribute((const void*)attn_mma_kernel, cudaFuncAttributeMaxDynamicSharedMemorySize, smemA);

    ln_kernel<<<ROWS, 256>>>(x, xn, ln_g, ln_b, IND);
    ctx_kernel<<<BB * MM, 256>>>(c_emb, ctx_ln_g, ctx_ln_b, W_ctx, b_ctx, kext, vext);
    pack_ext_kernel<<<(BB * HH * (NKEYS - NN) * DD) / 256, 256>>>(kext, vext, null_kv, kt, vt);
    // Q projection
    mma_gemm<1,0><<<dim3((HH * DD) / 128, ROWS / 128), 256, smem1>>>(
        xn, W_q, qb, ROWS, HH * DD, IND, nullptr, nullptr);
    // KV projection with fused interleaved pack epilogue
    mma_gemm<1,1><<<dim3(KVW / 128, ROWS / 128), 256, smem1>>>(
        xn, W_kv, nullptr, ROWS, KVW, IND, kt, vt);
    // attention (4 warps, 32 q-rows per warp, LDS.64 fragments)
    attn_mma_kernel<<<dim3(NN / 128, HH, BB), 128, smemA>>>(qb, kt, vt, attn);
    // output projection (split-A for accuracy)
    mma_gemm<2,0><<<dim3(IND / 128, ROWS / 128), 256, smem2>>>(
        attn, W_out, proj, ROWS, IND, IND, nullptr, nullptr);
    ln_kernel<<<ROWS, 256>>>(proj, out, out_ln_g, out_ln_b, IND);
}

// round 16
// speedup vs baseline: 1.0672x; 1.0561x over previous
#include <cuda_runtime.h>
#include <cuda_bf16.h>
#include <math.h>

// Problem constants
#define BB   2
#define NN   2048
#define MM   128
#define HH   16
#define DD   64
#define IND  1024
#define CTXD 768
#define ROWS (BB*NN)          // 4096
#define KVW  (2*HH*DD)        // 2048
#define KEXT 129              // 1 null + 128 ctx keys

// attention tiling
#define NKEYS  2240           // 2048 self + 129 ext, padded to 35*64
#define NTILES 35
#define LIMIT  2177
#define SPITCH 68

// mma gemm tiling (R6-proven: 8 warps, 64x32 warp tiles, 256 threads)
#define APITCH 20
#define BPITCH 136
#define ATILE  (128*APITCH)
#define BTILE  (16*BPITCH)

// ---------------- scratch (static device globals; no allocation) -------------
__device__ float g_xn  [ROWS*IND];
__device__ float g_q   [ROWS*HH*DD];
__device__ float g_kext[BB*KEXT*DD];
__device__ float g_vext[BB*KEXT*DD];
__device__ float g_kt  [BB*HH*NKEYS*DD];   // K packed  [b][h][key][d]  (tf32 bits)
__device__ float g_vt  [BB*HH*DD*NKEYS];   // V^T packed [b][h][d][key] (tf32 bits)
__device__ float g_attn[ROWS*HH*DD];
__device__ float g_proj[ROWS*IND];

// ---------------- tf32 helpers -------------------------------------------------
__device__ __forceinline__ unsigned f2tf32(float x) {
    unsigned r; asm("cvt.rna.tf32.f32 %0, %1;" : "=r"(r) : "f"(x)); return r;
}
__device__ __forceinline__ float tf32f(float x) {
    return __uint_as_float(f2tf32(x));
}

#define MMA_TF32(c, a, b0_, b1_)                                               \
    asm volatile("mma.sync.aligned.m16n8k8.row.col.f32.tf32.tf32.f32 "         \
                 "{%0,%1,%2,%3}, {%4,%5,%6,%7}, {%8,%9}, {%0,%1,%2,%3};"       \
                 : "+f"((c)[0]), "+f"((c)[1]), "+f"((c)[2]), "+f"((c)[3])      \
                 : "r"((a)[0]), "r"((a)[1]), "r"((a)[2]), "r"((a)[3]),         \
                   "r"(b0_), "r"(b1_))

// ---------------- block reduction helper -------------------------------------
__device__ __forceinline__ float block_reduce_sum(float v, float* sbuf) {
    __syncthreads();
    int lane = threadIdx.x & 31, warp = threadIdx.x >> 5;
    #pragma unroll
    for (int o = 16; o; o >>= 1) v += __shfl_xor_sync(0xffffffffu, v, o);
    if (lane == 0) sbuf[warp] = v;
    __syncthreads();
    int nw = (blockDim.x + 31) >> 5;
    v = (threadIdx.x < nw) ? sbuf[threadIdx.x] : 0.0f;
    if (warp == 0) {
        #pragma unroll
        for (int o = 16; o; o >>= 1) v += __shfl_xor_sync(0xffffffffu, v, o);
        if (lane == 0) sbuf[0] = v;
    }
    __syncthreads();
    return sbuf[0];
}

// ---------------- layernorm (one block per row) -------------------------------
__global__ void ln_kernel(const float* __restrict__ in, float* __restrict__ out,
                          const float* __restrict__ g, const float* __restrict__ b,
                          int C) {
    __shared__ float sbuf[32];
    const float* x = in + (size_t)blockIdx.x * C;
    float s = 0.f, s2 = 0.f;
    for (int i = threadIdx.x; i < C; i += blockDim.x) {
        float v = x[i]; s += v; s2 += v * v;
    }
    s  = block_reduce_sum(s,  sbuf);
    s2 = block_reduce_sum(s2, sbuf);
    float mean = s / C;
    float rstd = rsqrtf(s2 / C - mean * mean + 1e-5f);
    float* o = out + (size_t)blockIdx.x * C;
    for (int i = threadIdx.x; i < C; i += blockDim.x)
        o[i] = (x[i] - mean) * rstd * g[i] + b[i];
}

// ---------------- ctx branch: LN(768) + GEMV(768x128) fused --------------------
__global__ void ctx_kernel(const float* __restrict__ c_emb,
                           const float* __restrict__ g, const float* __restrict__ b,
                           const float* __restrict__ W,
                           const float* __restrict__ bctx,
                           float* __restrict__ kext, float* __restrict__ vext) {
    __shared__ float row[CTXD];
    __shared__ float sbuf[32];
    int rid = blockIdx.x;
    int bb = rid >> 7, m = rid & 127;
    const float* x = c_emb + (size_t)rid * CTXD;
    float s = 0.f, s2 = 0.f;
    for (int i = threadIdx.x; i < CTXD; i += blockDim.x) {
        float v = x[i]; row[i] = v; s += v; s2 += v * v;
    }
    s  = block_reduce_sum(s,  sbuf);
    s2 = block_reduce_sum(s2, sbuf);
    float mean = s / CTXD;
    float rstd = rsqrtf(s2 / CTXD - mean * mean + 1e-5f);
    for (int i = threadIdx.x; i < CTXD; i += blockDim.x)
        row[i] = (row[i] - mean) * rstd * g[i] + b[i];
    __syncthreads();
    if (threadIdx.x < 128) {
        int j = threadIdx.x;
        float acc = bctx[j];
        #pragma unroll 8
        for (int d = 0; d < CTXD; d++) acc += row[d] * W[d * 128 + j];
        if (j < DD) kext[((size_t)bb * KEXT + m + 1) * DD + j] = acc;
        else        vext[((size_t)bb * KEXT + m + 1) * DD + (j - DD)] = acc;
    }
}

// ---------------- pack EXT region (keys 2048..2239) into Kp / Vt ---------------
// Flattened: grid 1536 x 256 threads, one element per thread. Null row folded in.
__global__ void pack_ext_kernel(const float* __restrict__ kext,
                                const float* __restrict__ vext,
                                const float* __restrict__ null_kv,
                                float* __restrict__ Kp, float* __restrict__ Vt) {
    const int NE = NKEYS - NN;            // 192
    int idx = blockIdx.x * 256 + threadIdx.x;
    int d  = idx & 63;
    int kl = (idx >> 6) % NE;
    int bh = idx / (NE * 64);
    int b = bh >> 4;
    int key = NN + kl;
    float kvval = 0.f, vvval = 0.f;
    if (kl == 0) {
        kvval = tf32f(null_kv[d]);
        vvval = tf32f(null_kv[DD + d]);
    } else if (key < LIMIT) {
        size_t off = ((size_t)b * KEXT + kl) * DD + d;
        kvval = tf32f(kext[off]);
        vvval = tf32f(vext[off]);
    }
    Kp[((size_t)bh * NKEYS + key) * DD + d] = kvval;
    Vt[((size_t)bh * DD + d) * NKEYS + key] = vvval;
}

// ---------------- tf32 mma GEMM: C = A(MxK) x B(KxN), row-major -----------------
// R6/R13-proven config: 128x128 CTA tile, BK=16, 8 warps (2x4), warp tile 64x32.
// SPLITA=1: plain tf32. SPLITA=2: A split hi/lo (2 passes, unused currently).
// MODE=0: write C.  MODE=1: KV-pack epilogue -> write Kp / Vt.
template<int SPLITA, int MODE>
__global__ __launch_bounds__(256) void mma_gemm(
        const float* __restrict__ A, const float* __restrict__ B,
        float* __restrict__ C, int M, int N, int K,
        float* __restrict__ Kp, float* __restrict__ Vt) {
    extern __shared__ float smf[];
    const int PER = SPLITA * ATILE + BTILE;

    int tid = threadIdx.x;
    int w = tid >> 5, lane = tid & 31, g = lane >> 2, t = lane & 3;
    int wm = (w >> 2) * 64, wn = (w & 3) * 32;

    const float* Ab = A + (size_t)(blockIdx.y * 128) * K;
    const float* Bb = B + (size_t)(blockIdx.x * 128);

    int aRow = tid >> 1,  aCol = (tid & 1) * 8;
    int bRow = tid >> 4,  bCol = (tid & 15) * 8;

    float acc[4][4][4];
    #pragma unroll
    for (int mi = 0; mi < 4; mi++)
        #pragma unroll
        for (int nj = 0; nj < 4; nj++)
            #pragma unroll
            for (int q = 0; q < 4; q++) acc[mi][nj][q] = 0.f;

    float4 pa0, pa1, pb0, pb1;
    {
        const float* ap = Ab + (size_t)aRow * K + aCol;
        pa0 = *(const float4*)ap; pa1 = *(const float4*)(ap + 4);
        const float* bp = Bb + (size_t)bRow * N + bCol;
        pb0 = *(const float4*)bp; pb1 = *(const float4*)(bp + 4);
    }
    // store tile 0
    {
        float* base = smf;
        float* AhP = base;
        float* BhP = base + SPLITA * ATILE;
        float4 h0 = make_float4(tf32f(pa0.x), tf32f(pa0.y), tf32f(pa0.z), tf32f(pa0.w));
        float4 h1 = make_float4(tf32f(pa1.x), tf32f(pa1.y), tf32f(pa1.z), tf32f(pa1.w));
        *(float4*)&AhP[aRow * APITCH + aCol]     = h0;
        *(float4*)&AhP[aRow * APITCH + aCol + 4] = h1;
        if (SPLITA == 2) {
            float* AlP = base + ATILE;
            *(float4*)&AlP[aRow * APITCH + aCol] =
                make_float4(tf32f(pa0.x - h0.x), tf32f(pa0.y - h0.y), tf32f(pa0.z - h0.z), tf32f(pa0.w - h0.w));
            *(float4*)&AlP[aRow * APITCH + aCol + 4] =
                make_float4(tf32f(pa1.x - h1.x), tf32f(pa1.y - h1.y), tf32f(pa1.z - h1.z), tf32f(pa1.w - h1.w));
        }
        *(float4*)&BhP[bRow * BPITCH + bCol] =
            make_float4(tf32f(pb0.x), tf32f(pb0.y), tf32f(pb0.z), tf32f(pb0.w));
        *(float4*)&BhP[bRow * BPITCH + bCol + 4] =
            make_float4(tf32f(pb1.x), tf32f(pb1.y), tf32f(pb1.z), tf32f(pb1.w));
    }
    __syncthreads();

    int buf = 0;
    for (int k0 = 0; k0 < K; k0 += 16) {
        bool next = (k0 + 16) < K;
        if (next) {
            const float* ap = Ab + (size_t)aRow * K + (k0 + 16) + aCol;
            pa0 = *(const float4*)ap; pa1 = *(const float4*)(ap + 4);
            const float* bp = Bb + (size_t)(k0 + 16 + bRow) * N + bCol;
            pb0 = *(const float4*)bp; pb1 = *(const float4*)(bp + 4);
        }
        float* base = smf + buf * PER;
        const float* AhP = base;
        const float* AlP = base + ATILE;
        const float* BhP = base + SPLITA * ATILE;
        #pragma unroll
        for (int kk = 0; kk < 2; kk++) {
            int k = kk * 8;
            unsigned aF[4][4], bF[4][2];
            #pragma unroll
            for (int mi = 0; mi < 4; mi++) {
                const float* ap2 = AhP + (wm + mi * 16 + g) * APITCH + k + t;
                aF[mi][0] = __float_as_uint(ap2[0]);
                aF[mi][1] = __float_as_uint(ap2[8 * APITCH]);
                aF[mi][2] = __float_as_uint(ap2[4]);
                aF[mi][3] = __float_as_uint(ap2[8 * APITCH + 4]);
            }
            #pragma unroll
            for (int nj = 0; nj < 4; nj++) {
                const float* bp2 = BhP + (k + t) * BPITCH + wn + nj * 8 + g;
                bF[nj][0] = __float_as_uint(bp2[0]);
                bF[nj][1] = __float_as_uint(bp2[4 * BPITCH]);
            }
            #pragma unroll
            for (int mi = 0; mi < 4; mi++)
                #pragma unroll
                for (int nj = 0; nj < 4; nj++)
                    MMA_TF32(acc[mi][nj], aF[mi], bF[nj][0], bF[nj][1]);
            if (SPLITA == 2) {
                unsigned aL[4][4];
                #pragma unroll
                for (int mi = 0; mi < 4; mi++) {
                    const float* ap2 = AlP + (wm + mi * 16 + g) * APITCH + k + t;
                    aL[mi][0] = __float_as_uint(ap2[0]);
                    aL[mi][1] = __float_as_uint(ap2[8 * APITCH]);
                    aL[mi][2] = __float_as_uint(ap2[4]);
                    aL[mi][3] = __float_as_uint(ap2[8 * APITCH + 4]);
                }
                #pragma unroll
                for (int mi = 0; mi < 4; mi++)
                    #pragma unroll
                    for (int nj = 0; nj < 4; nj++)
                        MMA_TF32(acc[mi][nj], aL[mi], bF[nj][0], bF[nj][1]);
            }
        }
        if (next) {
            float* nb = smf + (buf ^ 1) * PER;
            float* AhP2 = nb;
            float* BhP2 = nb + SPLITA * ATILE;
            float4 h0 = make_float4(tf32f(pa0.x), tf32f(pa0.y), tf32f(pa0.z), tf32f(pa0.w));
            float4 h1 = make_float4(tf32f(pa1.x), tf32f(pa1.y), tf32f(pa1.z), tf32f(pa1.w));
            *(float4*)&AhP2[aRow * APITCH + aCol]     = h0;
            *(float4*)&AhP2[aRow * APITCH + aCol + 4] = h1;
            if (SPLITA == 2) {
                float* AlP2 = nb + ATILE;
                *(float4*)&AlP2[aRow * APITCH + aCol] =
                    make_float4(tf32f(pa0.x - h0.x), tf32f(pa0.y - h0.y), tf32f(pa0.z - h0.z), tf32f(pa0.w - h0.w));
                *(float4*)&AlP2[aRow * APITCH + aCol + 4] =
                    make_float4(tf32f(pa1.x - h1.x), tf32f(pa1.y - h1.y), tf32f(pa1.z - h1.z), tf32f(pa1.w - h1.w));
            }
            *(float4*)&BhP2[bRow * BPITCH + bCol] =
                make_float4(tf32f(pb0.x), tf32f(pb0.y), tf32f(pb0.z), tf32f(pb0.w));
            *(float4*)&BhP2[bRow * BPITCH + bCol + 4] =
                make_float4(tf32f(pb1.x), tf32f(pb1.y), tf32f(pb1.z), tf32f(pb1.w));
            __syncthreads();
            buf ^= 1;
        }
    }

    if (MODE == 0) {
        #pragma unroll
        for (int mi = 0; mi < 4; mi++) {
            int row = blockIdx.y * 128 + wm + mi * 16 + g;
            #pragma unroll
            for (int nj = 0; nj < 4; nj++) {
                int col = blockIdx.x * 128 + wn + nj * 8 + 2 * t;
                *(float2*)&C[(size_t)row * N + col]       = make_float2(acc[mi][nj][0], acc[mi][nj][1]);
                *(float2*)&C[(size_t)(row + 8) * N + col] = make_float2(acc[mi][nj][2], acc[mi][nj][3]);
            }
        }
    } else {
        // KV pack epilogue: row = token, col -> (s, h, d); write Kp / Vt (tf32).
        #pragma unroll
        for (int mi = 0; mi < 4; mi++) {
            int row = blockIdx.y * 128 + wm + mi * 16 + g;
            #pragma unroll
            for (int nj = 0; nj < 4; nj++) {
                int col = blockIdx.x * 128 + wn + nj * 8 + 2 * t;
                int s = col >> 10, h = (col >> 6) & 15, d = col & 63;
                #pragma unroll
                for (int half = 0; half < 2; half++) {
                    int tok = row + half * 8;
                    int b = tok >> 11, n = tok & 2047;
                    int bh = b * HH + h;
                    float v0 = tf32f(acc[mi][nj][half * 2 + 0]);
                    float v1 = tf32f(acc[mi][nj][half * 2 + 1]);
                    if (s == 0) {
                        *(float2*)&Kp[((size_t)bh * NKEYS + n) * DD + d] = make_float2(v0, v1);
                    } else {
                        Vt[((size_t)bh * DD + d)     * NKEYS + n] = v0;
                        Vt[((size_t)bh * DD + d + 1) * NKEYS + n] = v1;
                    }
                }
            }
        }
    }
}

// ---------------- flash attention on tensor cores (tf32 mma.sync) --------------
// R13-proven: 4 warps, 32 q-rows/warp (two 16-row A blocks); B-fragments feed
// two MMAs each. P in private smem region.
__global__ __launch_bounds__(128) void attn_mma_kernel(
        const float* __restrict__ qb,
        const float* __restrict__ Kp,
        const float* __restrict__ Vt,
        float* __restrict__ outb) {
    extern __shared__ float smem[];
    float* Ksm = smem;                    // 64 rows
    float* Vsm = smem + 64 * SPITCH;      // 64 rows
    float* Psm = smem + 128 * SPITCH;     // 128 rows (warp-private 32-row slices)
    int b = blockIdx.z, h = blockIdx.y;
    int tid = threadIdx.x;
    int w = tid >> 5, lane = tid & 31;
    int g = lane >> 2, t = lane & 3;
    int qa = blockIdx.x * 128 + w * 32 + g;   // rows qa, +8, +16, +24

    unsigned qA[2][8][4];
    #pragma unroll
    for (int blk = 0; blk < 2; blk++) {
        const float* q0 = qb + ((size_t)(b * NN + qa + blk * 16)) * (HH * DD) + h * DD;
        const float* q1 = q0 + 8 * (HH * DD);
        #pragma unroll
        for (int kk = 0; kk < 8; kk++) {
            qA[blk][kk][0] = f2tf32(q0[kk * 8 + t]     * 0.125f);
            qA[blk][kk][1] = f2tf32(q1[kk * 8 + t]     * 0.125f);
            qA[blk][kk][2] = f2tf32(q0[kk * 8 + t + 4] * 0.125f);
            qA[blk][kk][3] = f2tf32(q1[kk * 8 + t + 4] * 0.125f);
        }
    }

    const float* Kg = Kp + ((size_t)(b * HH + h)) * NKEYS * DD;
    const float* Vg = Vt + ((size_t)(b * HH + h)) * DD * NKEYS;

    float m[4] = {-1e30f, -1e30f, -1e30f, -1e30f};
    float l[4] = {0.f, 0.f, 0.f, 0.f};
    float oC[2][8][4];
    #pragma unroll
    for (int blk = 0; blk < 2; blk++)
        #pragma unroll
        for (int nt = 0; nt < 8; nt++)
            #pragma unroll
            for (int j = 0; j < 4; j++) oC[blk][nt][j] = 0.f;

    float* Prow[4];
    #pragma unroll
    for (int r = 0; r < 4; r++) Prow[r] = &Psm[(w * 32 + r * 8 + g) * SPITCH];

    for (int tile = 0; tile < NTILES; tile++) {
        int tb = tile * 64;
        __syncthreads();
        #pragma unroll
        for (int i = 0; i < 8; i++) {
            int idx = tid + i * 128;
            int r = idx >> 4, c = (idx & 15) * 4;
            *(float4*)&Ksm[r * SPITCH + c] = *(const float4*)&Kg[(size_t)(tb + r) * DD + c];
            *(float4*)&Vsm[r * SPITCH + c] = *(const float4*)&Vg[(size_t)r * NKEYS + tb + c];
        }
        __syncthreads();

        // ---- S = Q * K^T for both row blocks (shared K fragments) ----
        float sC[2][8][4];
        #pragma unroll
        for (int blk = 0; blk < 2; blk++)
            #pragma unroll
            for (int nt = 0; nt < 8; nt++)
                #pragma unroll
                for (int j = 0; j < 4; j++) sC[blk][nt][j] = 0.f;
        #pragma unroll
        for (int kk = 0; kk < 8; kk++) {
            #pragma unroll
            for (int nt = 0; nt < 8; nt++) {
                const float* kr = &Ksm[(nt * 8 + g) * SPITCH + kk * 8 + t];
                unsigned b0 = __float_as_uint(kr[0]);
                unsigned b1 = __float_as_uint(kr[4]);
                MMA_TF32(sC[0][nt], qA[0][kk], b0, b1);
                MMA_TF32(sC[1][nt], qA[1][kk], b0, b1);
            }
        }

        // ---- pad mask (only the last tile has pad keys) ----
        if (tile == NTILES - 1) {
            int lim = LIMIT - tb;
            #pragma unroll
            for (int nt = 0; nt < 8; nt++) {
                int c0 = nt * 8 + 2 * t, c1 = c0 + 1;
                #pragma unroll
                for (int blk = 0; blk < 2; blk++) {
                    if (c0 >= lim) { sC[blk][nt][0] = -1e30f; sC[blk][nt][2] = -1e30f; }
                    if (c1 >= lim) { sC[blk][nt][1] = -1e30f; sC[blk][nt][3] = -1e30f; }
                }
            }
        }

        // ---- online softmax for 4 row groups ----
        #pragma unroll
        for (int blk = 0; blk < 2; blk++) {
            float tmax0 = -1e30f, tmax1 = -1e30f;
            #pragma unroll
            for (int nt = 0; nt < 8; nt++) {
                tmax0 = fmaxf(tmax0, fmaxf(sC[blk][nt][0], sC[blk][nt][1]));
                tmax1 = fmaxf(tmax1, fmaxf(sC[blk][nt][2], sC[blk][nt][3]));
            }
            tmax0 = fmaxf(tmax0, __shfl_xor_sync(0xffffffffu, tmax0, 1));
            tmax0 = fmaxf(tmax0, __shfl_xor_sync(0xffffffffu, tmax0, 2));
            tmax1 = fmaxf(tmax1, __shfl_xor_sync(0xffffffffu, tmax1, 1));
            tmax1 = fmaxf(tmax1, __shfl_xor_sync(0xffffffffu, tmax1, 2));

            int r0 = blk * 2, r1 = blk * 2 + 1;
            float mn0 = fmaxf(m[r0], tmax0), mn1 = fmaxf(m[r1], tmax1);
            float corr0 = __expf(m[r0] - mn0), corr1 = __expf(m[r1] - mn1);
            m[r0] = mn0; m[r1] = mn1;

            float ps0 = 0.f, ps1 = 0.f;
            #pragma unroll
            for (int nt = 0; nt < 8; nt++) {
                float p0 = __expf(sC[blk][nt][0] - mn0), p1 = __expf(sC[blk][nt][1] - mn0);
                float p2 = __expf(sC[blk][nt][2] - mn1), p3 = __expf(sC[blk][nt][3] - mn1);
                ps0 += p0 + p1; ps1 += p2 + p3;
                *(float2*)&Prow[r0][nt * 8 + 2 * t] = make_float2(tf32f(p0), tf32f(p1));
                *(float2*)&Prow[r1][nt * 8 + 2 * t] = make_float2(tf32f(p2), tf32f(p3));
                oC[blk][nt][0] *= corr0; oC[blk][nt][1] *= corr0;
                oC[blk][nt][2] *= corr1; oC[blk][nt][3] *= corr1;
            }
            l[r0] = l[r0] * corr0 + ps0;
            l[r1] = l[r1] * corr1 + ps1;
        }
        __syncwarp();                  // P rows are warp-private

        // ---- O += P * V for both blocks (shared V fragments) ----
        #pragma unroll
        for (int kk = 0; kk < 8; kk++) {
            unsigned a0[4], a1[4];
            a0[0] = __float_as_uint(Prow[0][kk * 8 + t]);
            a0[1] = __float_as_uint(Prow[1][kk * 8 + t]);
            a0[2] = __float_as_uint(Prow[0][kk * 8 + t + 4]);
            a0[3] = __float_as_uint(Prow[1][kk * 8 + t + 4]);
            a1[0] = __float_as_uint(Prow[2][kk * 8 + t]);
            a1[1] = __float_as_uint(Prow[3][kk * 8 + t]);
            a1[2] = __float_as_uint(Prow[2][kk * 8 + t + 4]);
            a1[3] = __float_as_uint(Prow[3][kk * 8 + t + 4]);
            #pragma unroll
            for (int nd = 0; nd < 8; nd++) {
                const float* vr = &Vsm[(nd * 8 + g) * SPITCH + kk * 8 + t];
                unsigned b0 = __float_as_uint(vr[0]);
                unsigned b1 = __float_as_uint(vr[4]);
                MMA_TF32(oC[0][nd], a0, b0, b1);
                MMA_TF32(oC[1][nd], a1, b0, b1);
            }
        }
    }

    // ---- epilogue ----
    #pragma unroll
    for (int r = 0; r < 4; r++) {
        l[r] += __shfl_xor_sync(0xffffffffu, l[r], 1);
        l[r] += __shfl_xor_sync(0xffffffffu, l[r], 2);
    }
    #pragma unroll
    for (int blk = 0; blk < 2; blk++) {
        float inv0 = 1.f / l[blk * 2], inv1 = 1.f / l[blk * 2 + 1];
        float* o0 = outb + ((size_t)(b * NN + qa + blk * 16)) * (HH * DD) + h * DD;
        float* o1 = o0 + 8 * (HH * DD);
        #pragma unroll
        for (int nt = 0; nt < 8; nt++) {
            *(float2*)&o0[nt * 8 + 2 * t] = make_float2(oC[blk][nt][0] * inv0, oC[blk][nt][1] * inv0);
            *(float2*)&o1[nt * 8 + 2 * t] = make_float2(oC[blk][nt][2] * inv1, oC[blk][nt][3] * inv1);
        }
    }
}

// ---------------- host launcher ------------------------------------------------
extern "C" void kernel_launch(void* const* d_in, const int* in_sizes, int n_in,
                              void* d_out, int out_size) {
    const float* x        = (const float*)d_in[0];
    const float* c_emb    = (const float*)d_in[1];
    const float* ln_g     = (const float*)d_in[2];
    const float* ln_b     = (const float*)d_in[3];
    const float* ctx_ln_g = (const float*)d_in[4];
    const float* ctx_ln_b = (const float*)d_in[5];
    const float* W_ctx    = (const float*)d_in[6];
    const float* b_ctx    = (const float*)d_in[7];
    const float* W_q      = (const float*)d_in[8];
    const float* W_kv     = (const float*)d_in[9];
    const float* null_kv  = (const float*)d_in[10];
    const float* W_out    = (const float*)d_in[11];
    const float* out_ln_g = (const float*)d_in[12];
    const float* out_ln_b = (const float*)d_in[13];
    float* out = (float*)d_out;

    float *xn, *qb, *kext, *vext, *kt, *vt, *attn, *proj;
    cudaGetSymbolAddress((void**)&xn,   g_xn);
    cudaGetSymbolAddress((void**)&qb,   g_q);
    cudaGetSymbolAddress((void**)&kext, g_kext);
    cudaGetSymbolAddress((void**)&vext, g_vext);
    cudaGetSymbolAddress((void**)&kt,   g_kt);
    cudaGetSymbolAddress((void**)&vt,   g_vt);
    cudaGetSymbolAddress((void**)&attn, g_attn);
    cudaGetSymbolAddress((void**)&proj, g_proj);

    const int smem1 = 2 * (1 * ATILE + BTILE) * 4;   // 37888 B
    const int smemA = 256 * SPITCH * 4;              // 69632 B (K+V+P)
    cudaFuncSetAttribute((const void*)mma_gemm<1,0>, cudaFuncAttributeMaxDynamicSharedMemorySize, smem1);
    cudaFuncSetAttribute((const void*)mma_gemm<1,1>, cudaFuncAttributeMaxDynamicSharedMemorySize, smem1);
    cudaFuncSetAttribute((const void*)attn_mma_kernel, cudaFuncAttributeMaxDynamicSharedMemorySize, smemA);

    ln_kernel<<<ROWS, 256>>>(x, xn, ln_g, ln_b, IND);
    ctx_kernel<<<BB * MM, 256>>>(c_emb, ctx_ln_g, ctx_ln_b, W_ctx, b_ctx, kext, vext);
    pack_ext_kernel<<<(BB * HH * (NKEYS - NN) * DD) / 256, 256>>>(kext, vext, null_kv, kt, vt);
    // Q projection
    mma_gemm<1,0><<<dim3((HH * DD) / 128, ROWS / 128), 256, smem1>>>(
        xn, W_q, qb, ROWS, HH * DD, IND, nullptr, nullptr);
    // KV projection with fused pack epilogue
    mma_gemm<1,1><<<dim3(KVW / 128, ROWS / 128), 256, smem1>>>(
        xn, W_kv, nullptr, ROWS, KVW, IND, kt, vt);
    // attention (4 warps, 32 q-rows per warp)
    attn_mma_kernel<<<dim3(NN / 128, HH, BB), 128, smemA>>>(qb, kt, vt, attn);
    // output projection — single-pass tf32 (split-A dropped; ~92us saved)
    mma_gemm<1,0><<<dim3(IND / 128, ROWS / 128), 256, smem1>>>(
        attn, W_out, proj, ROWS, IND, IND, nullptr, nullptr);
    ln_kernel<<<ROWS, 256>>>(proj, out, out_ln_g, out_ln_b, IND);
}

// round 17
// speedup vs baseline: 1.0674x; 1.0002x over previous
#include <cuda_runtime.h>
#include <cuda_bf16.h>
#include <math.h>

// Problem constants
#define BB   2
#define NN   2048
#define MM   128
#define HH   16
#define DD   64
#define IND  1024
#define CTXD 768
#define ROWS (BB*NN)          // 4096
#define KVW  (2*HH*DD)        // 2048
#define KEXT 129              // 1 null + 128 ctx keys

// attention tiling
#define NKEYS  2240           // 2048 self + 129 ext, padded to 35*64
#define NTILES 35
#define LIMIT  2177
#define SPITCH 68

// mma gemm tiling (R6-proven: 8 warps, 64x32 warp tiles, 256 threads)
#define APITCH 20
#define BPITCH 136
#define ATILE  (128*APITCH)
#define BTILE  (16*BPITCH)

// ---------------- scratch (static device globals; no allocation) -------------
__device__ float g_xn  [ROWS*IND];
__device__ float g_q   [ROWS*HH*DD];
__device__ float g_kext[BB*KEXT*DD];
__device__ float g_vext[BB*KEXT*DD];
__device__ float g_kt  [BB*HH*NKEYS*DD];   // K packed  [b][h][key][d]  (tf32 bits)
__device__ float g_vt  [BB*HH*DD*NKEYS];   // V^T packed [b][h][d][key] (tf32 bits)
__device__ float g_attn[ROWS*HH*DD];
__device__ float g_proj[ROWS*IND];

// ---------------- tf32 helpers -------------------------------------------------
__device__ __forceinline__ unsigned f2tf32(float x) {
    unsigned r; asm("cvt.rna.tf32.f32 %0, %1;" : "=r"(r) : "f"(x)); return r;
}
__device__ __forceinline__ float tf32f(float x) {
    return __uint_as_float(f2tf32(x));
}

#define MMA_TF32(c, a, b0_, b1_)                                               \
    asm volatile("mma.sync.aligned.m16n8k8.row.col.f32.tf32.tf32.f32 "         \
                 "{%0,%1,%2,%3}, {%4,%5,%6,%7}, {%8,%9}, {%0,%1,%2,%3};"       \
                 : "+f"((c)[0]), "+f"((c)[1]), "+f"((c)[2]), "+f"((c)[3])      \
                 : "r"((a)[0]), "r"((a)[1]), "r"((a)[2]), "r"((a)[3]),         \
                   "r"(b0_), "r"(b1_))

// ---------------- block reduction helper -------------------------------------
__device__ __forceinline__ float block_reduce_sum(float v, float* sbuf) {
    __syncthreads();
    int lane = threadIdx.x & 31, warp = threadIdx.x >> 5;
    #pragma unroll
    for (int o = 16; o; o >>= 1) v += __shfl_xor_sync(0xffffffffu, v, o);
    if (lane == 0) sbuf[warp] = v;
    __syncthreads();
    int nw = (blockDim.x + 31) >> 5;
    v = (threadIdx.x < nw) ? sbuf[threadIdx.x] : 0.0f;
    if (warp == 0) {
        #pragma unroll
        for (int o = 16; o; o >>= 1) v += __shfl_xor_sync(0xffffffffu, v, o);
        if (lane == 0) sbuf[0] = v;
    }
    __syncthreads();
    return sbuf[0];
}

// ---------------- layernorm (one block per row) -------------------------------
__global__ void ln_kernel(const float* __restrict__ in, float* __restrict__ out,
                          const float* __restrict__ g, const float* __restrict__ b,
                          int C) {
    __shared__ float sbuf[32];
    const float* x = in + (size_t)blockIdx.x * C;
    float s = 0.f, s2 = 0.f;
    for (int i = threadIdx.x; i < C; i += blockDim.x) {
        float v = x[i]; s += v; s2 += v * v;
    }
    s  = block_reduce_sum(s,  sbuf);
    s2 = block_reduce_sum(s2, sbuf);
    float mean = s / C;
    float rstd = rsqrtf(s2 / C - mean * mean + 1e-5f);
    float* o = out + (size_t)blockIdx.x * C;
    for (int i = threadIdx.x; i < C; i += blockDim.x)
        o[i] = (x[i] - mean) * rstd * g[i] + b[i];
}

// ---------------- ctx branch: LN(768) + GEMV(768x128) fused --------------------
__global__ void ctx_kernel(const float* __restrict__ c_emb,
                           const float* __restrict__ g, const float* __restrict__ b,
                           const float* __restrict__ W,
                           const float* __restrict__ bctx,
                           float* __restrict__ kext, float* __restrict__ vext) {
    __shared__ float row[CTXD];
    __shared__ float sbuf[32];
    int rid = blockIdx.x;
    int bb = rid >> 7, m = rid & 127;
    const float* x = c_emb + (size_t)rid * CTXD;
    float s = 0.f, s2 = 0.f;
    for (int i = threadIdx.x; i < CTXD; i += blockDim.x) {
        float v = x[i]; row[i] = v; s += v; s2 += v * v;
    }
    s  = block_reduce_sum(s,  sbuf);
    s2 = block_reduce_sum(s2, sbuf);
    float mean = s / CTXD;
    float rstd = rsqrtf(s2 / CTXD - mean * mean + 1e-5f);
    for (int i = threadIdx.x; i < CTXD; i += blockDim.x)
        row[i] = (row[i] - mean) * rstd * g[i] + b[i];
    __syncthreads();
    if (threadIdx.x < 128) {
        int j = threadIdx.x;
        float acc = bctx[j];
        #pragma unroll 8
        for (int d = 0; d < CTXD; d++) acc += row[d] * W[d * 128 + j];
        if (j < DD) kext[((size_t)bb * KEXT + m + 1) * DD + j] = acc;
        else        vext[((size_t)bb * KEXT + m + 1) * DD + (j - DD)] = acc;
    }
}

// ---------------- pack EXT region (keys 2048..2239) into Kp / Vt ---------------
__global__ void pack_ext_kernel(const float* __restrict__ kext,
                                const float* __restrict__ vext,
                                const float* __restrict__ null_kv,
                                float* __restrict__ Kp, float* __restrict__ Vt) {
    const int NE = NKEYS - NN;            // 192
    int idx = blockIdx.x * 256 + threadIdx.x;
    int d  = idx & 63;
    int kl = (idx >> 6) % NE;
    int bh = idx / (NE * 64);
    int b = bh >> 4;
    int key = NN + kl;
    float kvval = 0.f, vvval = 0.f;
    if (kl == 0) {
        kvval = tf32f(null_kv[d]);
        vvval = tf32f(null_kv[DD + d]);
    } else if (key < LIMIT) {
        size_t off = ((size_t)b * KEXT + kl) * DD + d;
        kvval = tf32f(kext[off]);
        vvval = tf32f(vext[off]);
    }
    Kp[((size_t)bh * NKEYS + key) * DD + d] = kvval;
    Vt[((size_t)bh * DD + d) * NKEYS + key] = vvval;
}

// ---------------- tf32 mma GEMM ------------------------------------------------
// R6/R13-proven loop: 128x128 CTA tile, BK=16, 8 warps (2x4), warp tile 64x32.
// MODE=0: plain C = A x B (N given).
// MODE=1: KV projection + pack epilogue (B = W_kv, N = 2048).
// MODE=2: MERGED Q+KV: blockIdx.x<8 -> Q path (B, N=1024, write C);
//         else -> KV path (B2, N=2048, pack epilogue). One launch, 768 CTAs,
//         removes the wave-quantization of two back-to-back latency-bound
//         launches. Bit-identical math to the separate launches.
template<int SPLITA, int MODE>
__global__ __launch_bounds__(256) void mma_gemm(
        const float* __restrict__ A, const float* __restrict__ B,
        const float* __restrict__ B2,
        float* __restrict__ C, int M, int N, int K,
        float* __restrict__ Kp, float* __restrict__ Vt) {
    extern __shared__ float smf[];
    const int PER = SPLITA * ATILE + BTILE;

    int tid = threadIdx.x;
    int w = tid >> 5, lane = tid & 31, g = lane >> 2, t = lane & 3;
    int wm = (w >> 2) * 64, wn = (w & 3) * 32;

    // per-CTA uniform path selection
    bool isQ = true;
    int bxl = blockIdx.x;
    const float* Bsel = B;
    int Neff = N;
    if (MODE == 2) {
        isQ = (blockIdx.x < 8);
        bxl = isQ ? blockIdx.x : blockIdx.x - 8;
        Bsel = isQ ? B : B2;
        Neff = isQ ? (HH * DD) : KVW;
    }

    const float* Ab = A + (size_t)(blockIdx.y * 128) * K;
    const float* Bb = Bsel + (size_t)(bxl * 128);

    int aRow = tid >> 1,  aCol = (tid & 1) * 8;
    int bRow = tid >> 4,  bCol = (tid & 15) * 8;

    float acc[4][4][4];
    #pragma unroll
    for (int mi = 0; mi < 4; mi++)
        #pragma unroll
        for (int nj = 0; nj < 4; nj++)
            #pragma unroll
            for (int q = 0; q < 4; q++) acc[mi][nj][q] = 0.f;

    float4 pa0, pa1, pb0, pb1;
    {
        const float* ap = Ab + (size_t)aRow * K + aCol;
        pa0 = *(const float4*)ap; pa1 = *(const float4*)(ap + 4);
        const float* bp = Bb + (size_t)bRow * Neff + bCol;
        pb0 = *(const float4*)bp; pb1 = *(const float4*)(bp + 4);
    }
    // store tile 0
    {
        float* base = smf;
        float* AhP = base;
        float* BhP = base + SPLITA * ATILE;
        float4 h0 = make_float4(tf32f(pa0.x), tf32f(pa0.y), tf32f(pa0.z), tf32f(pa0.w));
        float4 h1 = make_float4(tf32f(pa1.x), tf32f(pa1.y), tf32f(pa1.z), tf32f(pa1.w));
        *(float4*)&AhP[aRow * APITCH + aCol]     = h0;
        *(float4*)&AhP[aRow * APITCH + aCol + 4] = h1;
        if (SPLITA == 2) {
            float* AlP = base + ATILE;
            *(float4*)&AlP[aRow * APITCH + aCol] =
                make_float4(tf32f(pa0.x - h0.x), tf32f(pa0.y - h0.y), tf32f(pa0.z - h0.z), tf32f(pa0.w - h0.w));
            *(float4*)&AlP[aRow * APITCH + aCol + 4] =
                make_float4(tf32f(pa1.x - h1.x), tf32f(pa1.y - h1.y), tf32f(pa1.z - h1.z), tf32f(pa1.w - h1.w));
        }
        *(float4*)&BhP[bRow * BPITCH + bCol] =
            make_float4(tf32f(pb0.x), tf32f(pb0.y), tf32f(pb0.z), tf32f(pb0.w));
        *(float4*)&BhP[bRow * BPITCH + bCol + 4] =
            make_float4(tf32f(pb1.x), tf32f(pb1.y), tf32f(pb1.z), tf32f(pb1.w));
    }
    __syncthreads();

    int buf = 0;
    for (int k0 = 0; k0 < K; k0 += 16) {
        bool next = (k0 + 16) < K;
        if (next) {
            const float* ap = Ab + (size_t)aRow * K + (k0 + 16) + aCol;
            pa0 = *(const float4*)ap; pa1 = *(const float4*)(ap + 4);
            const float* bp = Bb + (size_t)(k0 + 16 + bRow) * Neff + bCol;
            pb0 = *(const float4*)bp; pb1 = *(const float4*)(bp + 4);
        }
        float* base = smf + buf * PER;
        const float* AhP = base;
        const float* AlP = base + ATILE;
        const float* BhP = base + SPLITA * ATILE;
        #pragma unroll
        for (int kk = 0; kk < 2; kk++) {
            int k = kk * 8;
            unsigned aF[4][4], bF[4][2];
            #pragma unroll
            for (int mi = 0; mi < 4; mi++) {
                const float* ap2 = AhP + (wm + mi * 16 + g) * APITCH + k + t;
                aF[mi][0] = __float_as_uint(ap2[0]);
                aF[mi][1] = __float_as_uint(ap2[8 * APITCH]);
                aF[mi][2] = __float_as_uint(ap2[4]);
                aF[mi][3] = __float_as_uint(ap2[8 * APITCH + 4]);
            }
            #pragma unroll
            for (int nj = 0; nj < 4; nj++) {
                const float* bp2 = BhP + (k + t) * BPITCH + wn + nj * 8 + g;
                bF[nj][0] = __float_as_uint(bp2[0]);
                bF[nj][1] = __float_as_uint(bp2[4 * BPITCH]);
            }
            #pragma unroll
            for (int mi = 0; mi < 4; mi++)
                #pragma unroll
                for (int nj = 0; nj < 4; nj++)
                    MMA_TF32(acc[mi][nj], aF[mi], bF[nj][0], bF[nj][1]);
            if (SPLITA == 2) {
                unsigned aL[4][4];
                #pragma unroll
                for (int mi = 0; mi < 4; mi++) {
                    const float* ap2 = AlP + (wm + mi * 16 + g) * APITCH + k + t;
                    aL[mi][0] = __float_as_uint(ap2[0]);
                    aL[mi][1] = __float_as_uint(ap2[8 * APITCH]);
                    aL[mi][2] = __float_as_uint(ap2[4]);
                    aL[mi][3] = __float_as_uint(ap2[8 * APITCH + 4]);
                }
                #pragma unroll
                for (int mi = 0; mi < 4; mi++)
                    #pragma unroll
                    for (int nj = 0; nj < 4; nj++)
                        MMA_TF32(acc[mi][nj], aL[mi], bF[nj][0], bF[nj][1]);
            }
        }
        if (next) {
            float* nb = smf + (buf ^ 1) * PER;
            float* AhP2 = nb;
            float* BhP2 = nb + SPLITA * ATILE;
            float4 h0 = make_float4(tf32f(pa0.x), tf32f(pa0.y), tf32f(pa0.z), tf32f(pa0.w));
            float4 h1 = make_float4(tf32f(pa1.x), tf32f(pa1.y), tf32f(pa1.z), tf32f(pa1.w));
            *(float4*)&AhP2[aRow * APITCH + aCol]     = h0;
            *(float4*)&AhP2[aRow * APITCH + aCol + 4] = h1;
            if (SPLITA == 2) {
                float* AlP2 = nb + ATILE;
                *(float4*)&AlP2[aRow * APITCH + aCol] =
                    make_float4(tf32f(pa0.x - h0.x), tf32f(pa0.y - h0.y), tf32f(pa0.z - h0.z), tf32f(pa0.w - h0.w));
                *(float4*)&AlP2[aRow * APITCH + aCol + 4] =
                    make_float4(tf32f(pa1.x - h1.x), tf32f(pa1.y - h1.y), tf32f(pa1.z - h1.z), tf32f(pa1.w - h1.w));
            }
            *(float4*)&BhP2[bRow * BPITCH + bCol] =
                make_float4(tf32f(pb0.x), tf32f(pb0.y), tf32f(pb0.z), tf32f(pb0.w));
            *(float4*)&BhP2[bRow * BPITCH + bCol + 4] =
                make_float4(tf32f(pb1.x), tf32f(pb1.y), tf32f(pb1.z), tf32f(pb1.w));
            __syncthreads();
            buf ^= 1;
        }
    }

    bool doC = (MODE == 0) || (MODE == 2 && isQ);
    if (doC) {
        int Nc = (MODE == 2) ? (HH * DD) : N;
        #pragma unroll
        for (int mi = 0; mi < 4; mi++) {
            int row = blockIdx.y * 128 + wm + mi * 16 + g;
            #pragma unroll
            for (int nj = 0; nj < 4; nj++) {
                int col = bxl * 128 + wn + nj * 8 + 2 * t;
                *(float2*)&C[(size_t)row * Nc + col]       = make_float2(acc[mi][nj][0], acc[mi][nj][1]);
                *(float2*)&C[(size_t)(row + 8) * Nc + col] = make_float2(acc[mi][nj][2], acc[mi][nj][3]);
            }
        }
    } else {
        // KV pack epilogue: row = token, col -> (s, h, d); write Kp / Vt (tf32).
        #pragma unroll
        for (int mi = 0; mi < 4; mi++) {
            int row = blockIdx.y * 128 + wm + mi * 16 + g;
            #pragma unroll
            for (int nj = 0; nj < 4; nj++) {
                int col = bxl * 128 + wn + nj * 8 + 2 * t;
                int s = col >> 10, h = (col >> 6) & 15, d = col & 63;
                #pragma unroll
                for (int half = 0; half < 2; half++) {
                    int tok = row + half * 8;
                    int b = tok >> 11, n = tok & 2047;
                    int bh = b * HH + h;
                    float v0 = tf32f(acc[mi][nj][half * 2 + 0]);
                    float v1 = tf32f(acc[mi][nj][half * 2 + 1]);
                    if (s == 0) {
                        *(float2*)&Kp[((size_t)bh * NKEYS + n) * DD + d] = make_float2(v0, v1);
                    } else {
                        Vt[((size_t)bh * DD + d)     * NKEYS + n] = v0;
                        Vt[((size_t)bh * DD + d + 1) * NKEYS + n] = v1;
                    }
                }
            }
        }
    }
}

// ---------------- flash attention on tensor cores (tf32 mma.sync) --------------
// R13-proven: 4 warps, 32 q-rows/warp (two 16-row A blocks); B-fragments feed
// two MMAs each. P in private smem region.
__global__ __launch_bounds__(128) void attn_mma_kernel(
        const float* __restrict__ qb,
        const float* __restrict__ Kp,
        const float* __restrict__ Vt,
        float* __restrict__ outb) {
    extern __shared__ float smem[];
    float* Ksm = smem;                    // 64 rows
    float* Vsm = smem + 64 * SPITCH;      // 64 rows
    float* Psm = smem + 128 * SPITCH;     // 128 rows (warp-private 32-row slices)
    int b = blockIdx.z, h = blockIdx.y;
    int tid = threadIdx.x;
    int w = tid >> 5, lane = tid & 31;
    int g = lane >> 2, t = lane & 3;
    int qa = blockIdx.x * 128 + w * 32 + g;   // rows qa, +8, +16, +24

    unsigned qA[2][8][4];
    #pragma unroll
    for (int blk = 0; blk < 2; blk++) {
        const float* q0 = qb + ((size_t)(b * NN + qa + blk * 16)) * (HH * DD) + h * DD;
        const float* q1 = q0 + 8 * (HH * DD);
        #pragma unroll
        for (int kk = 0; kk < 8; kk++) {
            qA[blk][kk][0] = f2tf32(q0[kk * 8 + t]     * 0.125f);
            qA[blk][kk][1] = f2tf32(q1[kk * 8 + t]     * 0.125f);
            qA[blk][kk][2] = f2tf32(q0[kk * 8 + t + 4] * 0.125f);
            qA[blk][kk][3] = f2tf32(q1[kk * 8 + t + 4] * 0.125f);
        }
    }

    const float* Kg = Kp + ((size_t)(b * HH + h)) * NKEYS * DD;
    const float* Vg = Vt + ((size_t)(b * HH + h)) * DD * NKEYS;

    float m[4] = {-1e30f, -1e30f, -1e30f, -1e30f};
    float l[4] = {0.f, 0.f, 0.f, 0.f};
    float oC[2][8][4];
    #pragma unroll
    for (int blk = 0; blk < 2; blk++)
        #pragma unroll
        for (int nt = 0; nt < 8; nt++)
            #pragma unroll
            for (int j = 0; j < 4; j++) oC[blk][nt][j] = 0.f;

    float* Prow[4];
    #pragma unroll
    for (int r = 0; r < 4; r++) Prow[r] = &Psm[(w * 32 + r * 8 + g) * SPITCH];

    for (int tile = 0; tile < NTILES; tile++) {
        int tb = tile * 64;
        __syncthreads();
        #pragma unroll
        for (int i = 0; i < 8; i++) {
            int idx = tid + i * 128;
            int r = idx >> 4, c = (idx & 15) * 4;
            *(float4*)&Ksm[r * SPITCH + c] = *(const float4*)&Kg[(size_t)(tb + r) * DD + c];
            *(float4*)&Vsm[r * SPITCH + c] = *(const float4*)&Vg[(size_t)r * NKEYS + tb + c];
        }
        __syncthreads();

        float sC[2][8][4];
        #pragma unroll
        for (int blk = 0; blk < 2; blk++)
            #pragma unroll
            for (int nt = 0; nt < 8; nt++)
                #pragma unroll
                for (int j = 0; j < 4; j++) sC[blk][nt][j] = 0.f;
        #pragma unroll
        for (int kk = 0; kk < 8; kk++) {
            #pragma unroll
            for (int nt = 0; nt < 8; nt++) {
                const float* kr = &Ksm[(nt * 8 + g) * SPITCH + kk * 8 + t];
                unsigned b0 = __float_as_uint(kr[0]);
                unsigned b1 = __float_as_uint(kr[4]);
                MMA_TF32(sC[0][nt], qA[0][kk], b0, b1);
                MMA_TF32(sC[1][nt], qA[1][kk], b0, b1);
            }
        }

        if (tile == NTILES - 1) {
            int lim = LIMIT - tb;
            #pragma unroll
            for (int nt = 0; nt < 8; nt++) {
                int c0 = nt * 8 + 2 * t, c1 = c0 + 1;
                #pragma unroll
                for (int blk = 0; blk < 2; blk++) {
                    if (c0 >= lim) { sC[blk][nt][0] = -1e30f; sC[blk][nt][2] = -1e30f; }
                    if (c1 >= lim) { sC[blk][nt][1] = -1e30f; sC[blk][nt][3] = -1e30f; }
                }
            }
        }

        #pragma unroll
        for (int blk = 0; blk < 2; blk++) {
            float tmax0 = -1e30f, tmax1 = -1e30f;
            #pragma unroll
            for (int nt = 0; nt < 8; nt++) {
                tmax0 = fmaxf(tmax0, fmaxf(sC[blk][nt][0], sC[blk][nt][1]));
                tmax1 = fmaxf(tmax1, fmaxf(sC[blk][nt][2], sC[blk][nt][3]));
            }
            tmax0 = fmaxf(tmax0, __shfl_xor_sync(0xffffffffu, tmax0, 1));
            tmax0 = fmaxf(tmax0, __shfl_xor_sync(0xffffffffu, tmax0, 2));
            tmax1 = fmaxf(tmax1, __shfl_xor_sync(0xffffffffu, tmax1, 1));
            tmax1 = fmaxf(tmax1, __shfl_xor_sync(0xffffffffu, tmax1, 2));

            int r0 = blk * 2, r1 = blk * 2 + 1;
            float mn0 = fmaxf(m[r0], tmax0), mn1 = fmaxf(m[r1], tmax1);
            float corr0 = __expf(m[r0] - mn0), corr1 = __expf(m[r1] - mn1);
            m[r0] = mn0; m[r1] = mn1;

            float ps0 = 0.f, ps1 = 0.f;
            #pragma unroll
            for (int nt = 0; nt < 8; nt++) {
                float p0 = __expf(sC[blk][nt][0] - mn0), p1 = __expf(sC[blk][nt][1] - mn0);
                float p2 = __expf(sC[blk][nt][2] - mn1), p3 = __expf(sC[blk][nt][3] - mn1);
                ps0 += p0 + p1; ps1 += p2 + p3;
                *(float2*)&Prow[r0][nt * 8 + 2 * t] = make_float2(tf32f(p0), tf32f(p1));
                *(float2*)&Prow[r1][nt * 8 + 2 * t] = make_float2(tf32f(p2), tf32f(p3));
                oC[blk][nt][0] *= corr0; oC[blk][nt][1] *= corr0;
                oC[blk][nt][2] *= corr1; oC[blk][nt][3] *= corr1;
            }
            l[r0] = l[r0] * corr0 + ps0;
            l[r1] = l[r1] * corr1 + ps1;
        }
        __syncwarp();                  // P rows are warp-private

        #pragma unroll
        for (int kk = 0; kk < 8; kk++) {
            unsigned a0[4], a1[4];
            a0[0] = __float_as_uint(Prow[0][kk * 8 + t]);
            a0[1] = __float_as_uint(Prow[1][kk * 8 + t]);
            a0[2] = __float_as_uint(Prow[0][kk * 8 + t + 4]);
            a0[3] = __float_as_uint(Prow[1][kk * 8 + t + 4]);
            a1[0] = __float_as_uint(Prow[2][kk * 8 + t]);
            a1[1] = __float_as_uint(Prow[3][kk * 8 + t]);
            a1[2] = __float_as_uint(Prow[2][kk * 8 + t + 4]);
            a1[3] = __float_as_uint(Prow[3][kk * 8 + t + 4]);
            #pragma unroll
            for (int nd = 0; nd < 8; nd++) {
                const float* vr = &Vsm[(nd * 8 + g) * SPITCH + kk * 8 + t];
                unsigned b0 = __float_as_uint(vr[0]);
                unsigned b1 = __float_as_uint(vr[4]);
                MMA_TF32(oC[0][nd], a0, b0, b1);
                MMA_TF32(oC[1][nd], a1, b0, b1);
            }
        }
    }

    #pragma unroll
    for (int r = 0; r < 4; r++) {
        l[r] += __shfl_xor_sync(0xffffffffu, l[r], 1);
        l[r] += __shfl_xor_sync(0xffffffffu, l[r], 2);
    }
    #pragma unroll
    for (int blk = 0; blk < 2; blk++) {
        float inv0 = 1.f / l[blk * 2], inv1 = 1.f / l[blk * 2 + 1];
        float* o0 = outb + ((size_t)(b * NN + qa + blk * 16)) * (HH * DD) + h * DD;
        float* o1 = o0 + 8 * (HH * DD);
        #pragma unroll
        for (int nt = 0; nt < 8; nt++) {
            *(float2*)&o0[nt * 8 + 2 * t] = make_float2(oC[blk][nt][0] * inv0, oC[blk][nt][1] * inv0);
            *(float2*)&o1[nt * 8 + 2 * t] = make_float2(oC[blk][nt][2] * inv1, oC[blk][nt][3] * inv1);
        }
    }
}

// ---------------- host launcher ------------------------------------------------
extern "C" void kernel_launch(void* const* d_in, const int* in_sizes, int n_in,
                              void* d_out, int out_size) {
    const float* x        = (const float*)d_in[0];
    const float* c_emb    = (const float*)d_in[1];
    const float* ln_g     = (const float*)d_in[2];
    const float* ln_b     = (const float*)d_in[3];
    const float* ctx_ln_g = (const float*)d_in[4];
    const float* ctx_ln_b = (const float*)d_in[5];
    const float* W_ctx    = (const float*)d_in[6];
    const float* b_ctx    = (const float*)d_in[7];
    const float* W_q      = (const float*)d_in[8];
    const float* W_kv     = (const float*)d_in[9];
    const float* null_kv  = (const float*)d_in[10];
    const float* W_out    = (const float*)d_in[11];
    const float* out_ln_g = (const float*)d_in[12];
    const float* out_ln_b = (const float*)d_in[13];
    float* out = (float*)d_out;

    float *xn, *qb, *kext, *vext, *kt, *vt, *attn, *proj;
    cudaGetSymbolAddress((void**)&xn,   g_xn);
    cudaGetSymbolAddress((void**)&qb,   g_q);
    cudaGetSymbolAddress((void**)&kext, g_kext);
    cudaGetSymbolAddress((void**)&vext, g_vext);
    cudaGetSymbolAddress((void**)&kt,   g_kt);
    cudaGetSymbolAddress((void**)&vt,   g_vt);
    cudaGetSymbolAddress((void**)&attn, g_attn);
    cudaGetSymbolAddress((void**)&proj, g_proj);

    const int smem1 = 2 * (1 * ATILE + BTILE) * 4;   // 37888 B
    const int smemA = 256 * SPITCH * 4;              // 69632 B (K+V+P)
    cudaFuncSetAttribute((const void*)mma_gemm<1,0>, cudaFuncAttributeMaxDynamicSharedMemorySize, smem1);
    cudaFuncSetAttribute((const void*)mma_gemm<1,2>, cudaFuncAttributeMaxDynamicSharedMemorySize, smem1);
    cudaFuncSetAttribute((const void*)attn_mma_kernel, cudaFuncAttributeMaxDynamicSharedMemorySize, smemA);

    ln_kernel<<<ROWS, 256>>>(x, xn, ln_g, ln_b, IND);
    ctx_kernel<<<BB * MM, 256>>>(c_emb, ctx_ln_g, ctx_ln_b, W_ctx, b_ctx, kext, vext);
    pack_ext_kernel<<<(BB * HH * (NKEYS - NN) * DD) / 256, 256>>>(kext, vext, null_kv, kt, vt);
    // MERGED Q + KV projection: 768 CTAs in one launch.
    // blockIdx.x<8 -> Q (writes qb); else -> KV (pack epilogue into kt/vt).
    mma_gemm<1,2><<<dim3(8 + KVW / 128, ROWS / 128), 256, smem1>>>(
        xn, W_q, W_kv, qb, ROWS, HH * DD, IND, kt, vt);
    // attention (4 warps, 32 q-rows per warp)
    attn_mma_kernel<<<dim3(NN / 128, HH, BB), 128, smemA>>>(qb, kt, vt, attn);
    // output projection — single-pass tf32
    mma_gemm<1,0><<<dim3(IND / 128, ROWS / 128), 256, smem1>>>(
        attn, W_out, nullptr, proj, ROWS, IND, IND, nullptr, nullptr);
    ln_kernel<<<ROWS, 256>>>(proj, out, out_ln_g, out_ln_b, IND);
}